// round 6
// baseline (speedup 1.0000x reference)
#include <cuda_runtime.h>
#include <cuda_bf16.h>
#include <math.h>
#include <stdint.h>

static constexpr int BKTOT = 16384;
static constexpr int RR    = 114688;

// ---------------- device-global scratch (allocation-free) ----------------
__device__ __align__(16) __nv_bfloat16 g_sp_h[16384*256], g_sp_l[16384*256];
__device__ __align__(16) __nv_bfloat16 g_xp_h[16384*576], g_xp_l[16384*576];
__device__ __align__(16) __nv_bfloat16 g_s1_h[16384*256], g_s1_l[16384*256];
__device__ __align__(16) float         g_uv  [16384*512];
__device__ __align__(16) __nv_bfloat16 g_co_h[114688*256], g_co_l[114688*256];
__device__ __align__(16) float         g_eff32[16384*256];
__device__ __align__(16) __nv_bfloat16 g_ef_h[16384*256], g_ef_l[16384*256];
__device__ __align__(16) __nv_bfloat16 g_eW [256*768];
__device__ __align__(16) __nv_bfloat16 g_uvW[512*768];
__device__ __align__(16) __nv_bfloat16 g_fW [384*768];     // [ctx 256 | att 128] triple
__device__ __align__(16) __nv_bfloat16 g_oW [256*3264];
__device__ __align__(16) float         g_epi[1536];        // bias|gamma|beta|W2 packed (384 each)

// ---------------- helpers ----------------
__device__ __forceinline__ uint32_t smem_u32(const void* p) {
    uint32_t a;
    asm("{ .reg .u64 t; cvta.to.shared.u64 t, %1; cvt.u32.u64 %0, t; }" : "=r"(a) : "l"(p));
    return a;
}
__device__ __forceinline__ void cpa16(uint32_t saddr, const void* g) {
    asm volatile("cp.async.cg.shared.global [%0], [%1], 16;" :: "r"(saddr), "l"(g));
}
#define CP_COMMIT() asm volatile("cp.async.commit_group;" ::: "memory")
#define CP_WAIT(n)  asm volatile("cp.async.wait_group %0;" :: "n"(n) : "memory")

__device__ __forceinline__ void mma_bf16(float* d, const uint32_t* a, const uint32_t* b) {
    asm volatile(
        "mma.sync.aligned.m16n8k16.row.col.f32.bf16.bf16.f32 "
        "{%0,%1,%2,%3}, {%4,%5,%6,%7}, {%8,%9}, {%0,%1,%2,%3};"
        : "+f"(d[0]), "+f"(d[1]), "+f"(d[2]), "+f"(d[3])
        : "r"(a[0]), "r"(a[1]), "r"(a[2]), "r"(a[3]), "r"(b[0]), "r"(b[1]));
}
__device__ __forceinline__ float ftanh(float x) {
    float t = fminf(fmaxf(2.f * x, -30.f), 30.f);
    float e = __expf(t);
    return (e - 1.f) / (e + 1.f);
}
__device__ __forceinline__ float fsigmoid(float z) {
    return 1.f / (1.f + __expf(-z));
}

// ---------------- prep kernels ----------------
__global__ void cvt_pad(__nv_bfloat16* __restrict__ dh, __nv_bfloat16* __restrict__ dl,
                        int DS, const float* __restrict__ src, int SC, int rows)
{
    int idx = blockIdx.x * blockDim.x + threadIdx.x;
    if (idx >= rows * DS) return;
    int r = idx / DS, c = idx - r * DS;
    float v = (c < SC) ? src[(size_t)r * SC + c] : 0.f;
    __nv_bfloat16 h = __float2bfloat16(v);
    dh[idx] = h;
    dl[idx] = __float2bfloat16(v - __bfloat162float(h));
}

// weight triple layout dst[n][KTRIP]: seg0 = hi, seg1 = lo, seg2 = hi (segments of KP)
__global__ void prep_w(__nv_bfloat16* __restrict__ dst, int KTRIP, int KP, int NP,
                       const float* __restrict__ W, int N0,
                       int b0, int v0, int b1, int v1, int b2, int v2)
{
    int idx = blockIdx.x * blockDim.x + threadIdx.x;
    if (idx >= NP * KTRIP) return;
    int n = idx / KTRIP, kk = idx - n * KTRIP;
    int seg = kk / KP, k = kk - seg * KP;
    bool lo = (seg == 1);
    int piece = (k >= 512) ? 2 : (k >= 256) ? 1 : 0;
    int off = k - ((piece == 2) ? 512 : piece * 256);
    int base  = (piece == 0) ? b0 : (piece == 1) ? b1 : b2;
    int valid = (piece == 0) ? v0 : (piece == 1) ? v1 : v2;
    float v = (n < N0 && off < valid) ? W[(size_t)(base + off) * N0 + n] : 0.f;
    __nv_bfloat16 h = __float2bfloat16(v);
    if (lo) h = __float2bfloat16(v - __bfloat162float(h));
    dst[idx] = h;
}

__global__ void epi_pack(float* __restrict__ dst,
                         const float* cb, const float* cg, const float* ct,
                         const float* ab, const float* ag, const float* at,
                         const float* w2)
{
    int i = blockIdx.x * blockDim.x + threadIdx.x;
    if (i >= 384) return;
    float b, g, t, w;
    if (i < 256) {
        b = (i < 250) ? cb[i] : 0.f;
        g = (i < 250) ? cg[i] : 0.f;
        t = (i < 250) ? ct[i] : 0.f;
        w = 0.f;
    } else {
        int j = i - 256;
        b = (j < 100) ? ab[j] : 0.f;
        g = (j < 100) ? ag[j] : 0.f;
        t = (j < 100) ? at[j] : 0.f;
        w = (j < 100) ? w2[j] : 0.f;
    }
    dst[i] = b; dst[384 + i] = g; dst[768 + i] = t; dst[1152 + i] = w;
}

// ---------------- HMMA fused GEMM ----------------
// A-triple per row: [a_hi | a_hi | a_lo] at load; Bw pre-baked [N][KTRIP]=[hi|lo|hi]
// GATHER: 0 plain (KP=256), 2 [s1|eff|x] (KP=1088)
// EPI: 0 bias?+fp32 store; 1 relu+LN -> hi/lo planes; 3 fused ctx+att+effect scatter
template<int BM, int BN, int KTRIP, int GATHER, int EPI>
__global__ void __launch_bounds__(256) hgemm(
    const __nv_bfloat16* __restrict__ A1h, const __nv_bfloat16* __restrict__ A1l,
    const __nv_bfloat16* __restrict__ A2h, const __nv_bfloat16* __restrict__ A2l,
    const __nv_bfloat16* __restrict__ A3h, const __nv_bfloat16* __restrict__ A3l,
    const __nv_bfloat16* __restrict__ Bw,
    const float* __restrict__ bias, const float* __restrict__ gamma, const float* __restrict__ beta,
    const float* __restrict__ W2, const float* __restrict__ b2,
    float* __restrict__ Cf, __nv_bfloat16* __restrict__ Chi, __nv_bfloat16* __restrict__ Clo,
    int N, int cstride)
{
    constexpr int PADK = 72;
    constexpr int NWM = BM / 32;
    constexpr int NWN = 8 / NWM;
    constexpr int NI  = BN / (8 * NWN);      // n-tiles of 8 per warp
    constexpr int NST = KTRIP / 64;

    extern __shared__ __align__(16) __nv_bfloat16 sm[];
    __nv_bfloat16* const Asm = sm;
    __nv_bfloat16* const Bsm = sm + 2 * BM * PADK;
    float* const red0 = (float*)(sm + 2 * (BM + BN) * PADK);   // 4 arrays of BM*NWN
    float* const red1 = red0 + BM * NWN;
    float* const red2 = red1 + BM * NWN;
    float* const red3 = red2 + BM * NWN;
    float* const attS = red3 + BM * NWN;                        // BM floats
    const uint32_t smb = smem_u32(sm);

    const int tid = threadIdx.x, w = tid >> 5, lane = tid & 31;
    const int g = lane >> 2, tq = lane & 3;
    const int wm = w % NWM, wn = w / NWM;
    const int row0 = blockIdx.x * BM;
    const int col0 = blockIdx.y * BN;
    Bw += (size_t)col0 * KTRIP;

    float acc[2][NI][4];
#pragma unroll
    for (int mi = 0; mi < 2; mi++)
#pragma unroll
        for (int ni = 0; ni < NI; ni++)
#pragma unroll
            for (int e = 0; e < 4; e++) acc[mi][ni][e] = 0.f;

    auto gatherA = [&](int gr, int kk) -> const __nv_bfloat16* {
        if (GATHER == 0) {
            int seg = kk >> 8, k = kk & 255;
            return ((seg == 2) ? A1l : A1h) + (size_t)gr * 256 + k;
        } else {
            int seg = kk / 1088, k = kk - seg * 1088;
            bool lo = (seg == 2);
            if (k < 256) return (lo ? A1l : A1h) + (size_t)gr * 256 + k;
            if (k < 512) return (lo ? A2l : A2h) + (size_t)gr * 256 + (k - 256);
            return (lo ? A3l : A3h) + (size_t)gr * 576 + (k - 512);
        }
    };

    auto loadStage = [&](int t, int st) {
        int kb = t * 64;
#pragma unroll
        for (int u = tid; u < BM * 8; u += 256) {
            int r = u >> 3, cq = u & 7;
            cpa16(smb + (((st * BM + r) * PADK + cq * 8) << 1), gatherA(row0 + r, kb + cq * 8));
        }
#pragma unroll
        for (int u = tid; u < BN * 8; u += 256) {
            int r = u >> 3, cq = u & 7;
            cpa16(smb + ((2 * BM * PADK + (st * BN + r) * PADK + cq * 8) << 1),
                  Bw + (size_t)r * KTRIP + kb + cq * 8);
        }
    };

    auto compute = [&](int st) {
        const __nv_bfloat16* At = Asm + st * BM * PADK;
        const __nv_bfloat16* Bt = Bsm + st * BN * PADK;
#pragma unroll
        for (int kk = 0; kk < 4; kk++) {
            uint32_t a[2][4], b[NI][2];
            const int k = kk * 16 + tq * 2;
#pragma unroll
            for (int mi = 0; mi < 2; mi++) {
                int r = wm * 32 + mi * 16 + g;
                a[mi][0] = *(const uint32_t*)(At + r * PADK + k);
                a[mi][1] = *(const uint32_t*)(At + (r + 8) * PADK + k);
                a[mi][2] = *(const uint32_t*)(At + r * PADK + k + 8);
                a[mi][3] = *(const uint32_t*)(At + (r + 8) * PADK + k + 8);
            }
#pragma unroll
            for (int ni = 0; ni < NI; ni++) {
                int r = wn * (NI * 8) + ni * 8 + g;
                b[ni][0] = *(const uint32_t*)(Bt + r * PADK + k);
                b[ni][1] = *(const uint32_t*)(Bt + r * PADK + k + 8);
            }
#pragma unroll
            for (int mi = 0; mi < 2; mi++)
#pragma unroll
                for (int ni = 0; ni < NI; ni++)
                    mma_bf16(acc[mi][ni], a[mi], b[ni]);
        }
    };

    loadStage(0, 0);
    CP_COMMIT();
    for (int t = 0; t < NST; t++) {
        if (t + 1 < NST) {
            loadStage(t + 1, (t + 1) & 1);
            CP_COMMIT();
            CP_WAIT(1);
        } else {
            CP_WAIT(0);
        }
        __syncthreads();
        compute(t & 1);
        __syncthreads();
    }

    // ---------------- epilogues ----------------
    if (EPI == 0) {
#pragma unroll
        for (int mi = 0; mi < 2; mi++) {
            int r0 = row0 + wm * 32 + mi * 16 + g;
#pragma unroll
            for (int ni = 0; ni < NI; ni++) {
                int c0 = wn * (NI * 8) + ni * 8 + tq * 2, c1 = c0 + 1;
                if (c0 < N) {
                    float bv = bias ? bias[c0] : 0.f;
                    Cf[(size_t)r0 * cstride + col0 + c0]       = acc[mi][ni][0] + bv;
                    Cf[(size_t)(r0 + 8) * cstride + col0 + c0] = acc[mi][ni][2] + bv;
                }
                if (c1 < N) {
                    float bv = bias ? bias[c1] : 0.f;
                    Cf[(size_t)r0 * cstride + col0 + c1]       = acc[mi][ni][1] + bv;
                    Cf[(size_t)(r0 + 8) * cstride + col0 + c1] = acc[mi][ni][3] + bv;
                }
            }
        }
        return;
    }

    if (EPI == 1) {
        float s[2][2] = {{0,0},{0,0}}, q[2][2] = {{0,0},{0,0}};
#pragma unroll
        for (int mi = 0; mi < 2; mi++)
#pragma unroll
            for (int ni = 0; ni < NI; ni++) {
                int c0 = wn * (NI * 8) + ni * 8 + tq * 2, c1 = c0 + 1;
                float b0v = (c0 < N) ? bias[c0] : 0.f;
                float b1v = (c1 < N) ? bias[c1] : 0.f;
                float v0 = fmaxf(acc[mi][ni][0] + b0v, 0.f);
                float v1 = fmaxf(acc[mi][ni][1] + b1v, 0.f);
                float v2 = fmaxf(acc[mi][ni][2] + b0v, 0.f);
                float v3 = fmaxf(acc[mi][ni][3] + b1v, 0.f);
                if (c0 >= N) { v0 = 0.f; v2 = 0.f; }
                if (c1 >= N) { v1 = 0.f; v3 = 0.f; }
                acc[mi][ni][0] = v0; acc[mi][ni][1] = v1;
                acc[mi][ni][2] = v2; acc[mi][ni][3] = v3;
                s[mi][0] += v0 + v1; q[mi][0] += v0 * v0 + v1 * v1;
                s[mi][1] += v2 + v3; q[mi][1] += v2 * v2 + v3 * v3;
            }
#pragma unroll
        for (int off = 1; off <= 2; off <<= 1)
#pragma unroll
            for (int mi = 0; mi < 2; mi++)
#pragma unroll
                for (int dr = 0; dr < 2; dr++) {
                    s[mi][dr] += __shfl_xor_sync(0xffffffffu, s[mi][dr], off);
                    q[mi][dr] += __shfl_xor_sync(0xffffffffu, q[mi][dr], off);
                }
        if (tq == 0)
#pragma unroll
            for (int mi = 0; mi < 2; mi++)
#pragma unroll
                for (int dr = 0; dr < 2; dr++) {
                    int r = wm * 32 + mi * 16 + g + 8 * dr;
                    red0[r * NWN + wn] = s[mi][dr];
                    red1[r * NWN + wn] = q[mi][dr];
                }
        __syncthreads();
        float mu[2][2], rs[2][2];
        const float invN = 1.f / (float)N;
#pragma unroll
        for (int mi = 0; mi < 2; mi++)
#pragma unroll
            for (int dr = 0; dr < 2; dr++) {
                int r = wm * 32 + mi * 16 + g + 8 * dr;
                float ss = 0.f, qq = 0.f;
#pragma unroll
                for (int xx = 0; xx < NWN; xx++) { ss += red0[r * NWN + xx]; qq += red1[r * NWN + xx]; }
                mu[mi][dr] = ss * invN;
                rs[mi][dr] = rsqrtf(qq * invN - mu[mi][dr] * mu[mi][dr] + 1e-5f);
            }
#pragma unroll
        for (int mi = 0; mi < 2; mi++) {
            int gr0 = row0 + wm * 32 + mi * 16 + g;
#pragma unroll
            for (int ni = 0; ni < NI; ni++) {
                int c0 = wn * (NI * 8) + ni * 8 + tq * 2, c1 = c0 + 1;
                float g0 = (c0 < N) ? gamma[c0] : 0.f, g1 = (c1 < N) ? gamma[c1] : 0.f;
                float t0 = (c0 < N) ? beta[c0] : 0.f,  t1 = (c1 < N) ? beta[c1]  : 0.f;
#pragma unroll
                for (int dr = 0; dr < 2; dr++) {
                    int gr = gr0 + 8 * dr;
                    float w0 = (c0 < N) ? (acc[mi][ni][2 * dr + 0] - mu[mi][dr]) * rs[mi][dr] * g0 + t0 : 0.f;
                    float w1 = (c1 < N) ? (acc[mi][ni][2 * dr + 1] - mu[mi][dr]) * rs[mi][dr] * g1 + t1 : 0.f;
                    __nv_bfloat16 h0 = __float2bfloat16(w0), h1 = __float2bfloat16(w1);
                    __nv_bfloat16 l0 = __float2bfloat16(w0 - __bfloat162float(h0));
                    __nv_bfloat16 l1 = __float2bfloat16(w1 - __bfloat162float(h1));
                    *(__nv_bfloat162*)(Chi + (size_t)gr * 256 + c0) = __halves2bfloat162(h0, h1);
                    *(__nv_bfloat162*)(Clo + (size_t)gr * 256 + c0) = __halves2bfloat162(l0, l1);
                }
            }
        }
        return;
    }

    // EPI == 3: cols 0-255 -> relu+LN(250)*att -> atomic eff32; cols 256-383 -> att score
    {
        float sC[2][2] = {{0,0},{0,0}}, qC[2][2] = {{0,0},{0,0}};
        float sA[2][2] = {{0,0},{0,0}}, qA[2][2] = {{0,0},{0,0}};
#pragma unroll
        for (int mi = 0; mi < 2; mi++)
#pragma unroll
            for (int ni = 0; ni < NI; ni++) {
                int c0 = wn * (NI * 8) + ni * 8 + tq * 2, c1 = c0 + 1;
                bool isA = (c0 >= 256);         // pair never straddles 256
                float b0v = bias[c0], b1v = bias[c1];
                float v0 = acc[mi][ni][0] + b0v, v1 = acc[mi][ni][1] + b1v;
                float v2 = acc[mi][ni][2] + b0v, v3 = acc[mi][ni][3] + b1v;
                if (isA) {
                    v0 = ftanh(v0); v1 = ftanh(v1); v2 = ftanh(v2); v3 = ftanh(v3);
                    if (c0 >= 356) { v0 = 0.f; v2 = 0.f; }
                    if (c1 >= 356) { v1 = 0.f; v3 = 0.f; }
                    sA[mi][0] += v0 + v1; qA[mi][0] += v0 * v0 + v1 * v1;
                    sA[mi][1] += v2 + v3; qA[mi][1] += v2 * v2 + v3 * v3;
                } else {
                    v0 = fmaxf(v0, 0.f); v1 = fmaxf(v1, 0.f);
                    v2 = fmaxf(v2, 0.f); v3 = fmaxf(v3, 0.f);
                    if (c0 >= 250) { v0 = 0.f; v2 = 0.f; }
                    if (c1 >= 250) { v1 = 0.f; v3 = 0.f; }
                    sC[mi][0] += v0 + v1; qC[mi][0] += v0 * v0 + v1 * v1;
                    sC[mi][1] += v2 + v3; qC[mi][1] += v2 * v2 + v3 * v3;
                }
                acc[mi][ni][0] = v0; acc[mi][ni][1] = v1;
                acc[mi][ni][2] = v2; acc[mi][ni][3] = v3;
            }
#pragma unroll
        for (int off = 1; off <= 2; off <<= 1)
#pragma unroll
            for (int mi = 0; mi < 2; mi++)
#pragma unroll
                for (int dr = 0; dr < 2; dr++) {
                    sC[mi][dr] += __shfl_xor_sync(0xffffffffu, sC[mi][dr], off);
                    qC[mi][dr] += __shfl_xor_sync(0xffffffffu, qC[mi][dr], off);
                    sA[mi][dr] += __shfl_xor_sync(0xffffffffu, sA[mi][dr], off);
                    qA[mi][dr] += __shfl_xor_sync(0xffffffffu, qA[mi][dr], off);
                }
        if (tq == 0)
#pragma unroll
            for (int mi = 0; mi < 2; mi++)
#pragma unroll
                for (int dr = 0; dr < 2; dr++) {
                    int r = wm * 32 + mi * 16 + g + 8 * dr;
                    red0[r * NWN + wn] = sC[mi][dr];
                    red1[r * NWN + wn] = qC[mi][dr];
                    red2[r * NWN + wn] = sA[mi][dr];
                    red3[r * NWN + wn] = qA[mi][dr];
                }
        __syncthreads();
        float muC[2][2], rsC[2][2], muA[2][2], rsA[2][2];
#pragma unroll
        for (int mi = 0; mi < 2; mi++)
#pragma unroll
            for (int dr = 0; dr < 2; dr++) {
                int r = wm * 32 + mi * 16 + g + 8 * dr;
                float sc = 0.f, qc = 0.f, sa = 0.f, qa = 0.f;
#pragma unroll
                for (int xx = 0; xx < NWN; xx++) {
                    sc += red0[r * NWN + xx]; qc += red1[r * NWN + xx];
                    sa += red2[r * NWN + xx]; qa += red3[r * NWN + xx];
                }
                muC[mi][dr] = sc * (1.f / 250.f);
                rsC[mi][dr] = rsqrtf(qc * (1.f / 250.f) - muC[mi][dr] * muC[mi][dr] + 1e-5f);
                muA[mi][dr] = sa * (1.f / 100.f);
                rsA[mi][dr] = rsqrtf(qa * (1.f / 100.f) - muA[mi][dr] * muA[mi][dr] + 1e-5f);
            }
        __syncthreads();
        // att dot(W2) -> sigmoid
        float d[2][2] = {{0,0},{0,0}};
#pragma unroll
        for (int mi = 0; mi < 2; mi++)
#pragma unroll
            for (int ni = 0; ni < NI; ni++) {
                int c0 = wn * (NI * 8) + ni * 8 + tq * 2, c1 = c0 + 1;
                if (c0 < 256) continue;
                float g0 = gamma[c0], g1 = gamma[c1];
                float t0 = beta[c0],  t1 = beta[c1];
                float w20 = W2[c0],   w21 = W2[c1];
#pragma unroll
                for (int dr = 0; dr < 2; dr++) {
                    float w0 = (acc[mi][ni][2 * dr + 0] - muA[mi][dr]) * rsA[mi][dr] * g0 + t0;
                    float w1 = (acc[mi][ni][2 * dr + 1] - muA[mi][dr]) * rsA[mi][dr] * g1 + t1;
                    d[mi][dr] += w0 * w20 + w1 * w21;
                }
            }
#pragma unroll
        for (int off = 1; off <= 2; off <<= 1)
#pragma unroll
            for (int mi = 0; mi < 2; mi++)
#pragma unroll
                for (int dr = 0; dr < 2; dr++)
                    d[mi][dr] += __shfl_xor_sync(0xffffffffu, d[mi][dr], off);
        if (tq == 0)
#pragma unroll
            for (int mi = 0; mi < 2; mi++)
#pragma unroll
                for (int dr = 0; dr < 2; dr++) {
                    int r = wm * 32 + mi * 16 + g + 8 * dr;
                    red0[r * NWN + wn] = d[mi][dr];
                }
        __syncthreads();
        if (wn == 0 && tq == 0) {
            float bb = b2[0];
#pragma unroll
            for (int mi = 0; mi < 2; mi++)
#pragma unroll
                for (int dr = 0; dr < 2; dr++) {
                    int r = wm * 32 + mi * 16 + g + 8 * dr;
                    float dd = 0.f;
#pragma unroll
                    for (int xx = 0; xx < NWN; xx++) dd += red0[r * NWN + xx];
                    attS[r] = fsigmoid(dd + bb);
                }
        }
        __syncthreads();
        // ctx LN * att -> atomic scatter into eff32[bk]
#pragma unroll
        for (int mi = 0; mi < 2; mi++)
#pragma unroll
            for (int ni = 0; ni < NI; ni++) {
                int c0 = wn * (NI * 8) + ni * 8 + tq * 2, c1 = c0 + 1;
                if (c0 >= 250) continue;
                float g0 = gamma[c0], g1 = gamma[c1];
                float t0 = beta[c0],  t1 = beta[c1];
                bool ok1 = (c1 < 250);
#pragma unroll
                for (int dr = 0; dr < 2; dr++) {
                    int rl = wm * 32 + mi * 16 + g + 8 * dr;
                    int gr = row0 + rl;
                    float av = attS[rl];
                    float* dst = g_eff32 + (size_t)(gr / 7) * 256;
                    float w0 = (acc[mi][ni][2 * dr + 0] - muC[mi][dr]) * rsC[mi][dr] * g0 + t0;
                    atomicAdd(dst + c0, w0 * av);
                    if (ok1) {
                        float w1 = (acc[mi][ni][2 * dr + 1] - muC[mi][dr]) * rsC[mi][dr] * g1 + t1;
                        atomicAdd(dst + c1, w1 * av);
                    }
                }
            }
    }
}

// ---------------- core combine: core[b,i,j] = LN(relu(U[b,i] + V[b,j] + bias)) ----------------
__global__ void __launch_bounds__(256) combine_core(
    const float* __restrict__ UV, const float* __restrict__ bias,
    const float* __restrict__ gamma, const float* __restrict__ beta,
    __nv_bfloat16* __restrict__ ch, __nv_bfloat16* __restrict__ cl)
{
    const int r    = blockIdx.x * 8 + (threadIdx.x >> 5);
    const int lane = threadIdx.x & 31;
    const int b = r / 56, rem = r - b * 56;
    const int i = rem / 7, jj = rem - i * 7;
    const int j = jj + (jj >= i ? 1 : 0);
    const float4* up = (const float4*)(UV + (size_t)(b * 8 + i) * 512);
    const float4* vp = (const float4*)(UV + (size_t)(b * 8 + j) * 512 + 256);

    const int c0 = lane * 8;
    float v[8];
#pragma unroll
    for (int h = 0; h < 2; h++) {
        float4 u4 = up[lane * 2 + h];
        float4 v4 = vp[lane * 2 + h];
        float* vv = v + h * 4;
        vv[0] = u4.x + v4.x; vv[1] = u4.y + v4.y;
        vv[2] = u4.z + v4.z; vv[3] = u4.w + v4.w;
    }
    float s = 0.f, q = 0.f;
#pragma unroll
    for (int e = 0; e < 8; e++) {
        int c = c0 + e;
        float x = (c < 250) ? fmaxf(v[e] + bias[c], 0.f) : 0.f;
        v[e] = x;
        s += x; q += x * x;
    }
#pragma unroll
    for (int off = 16; off > 0; off >>= 1) {
        s += __shfl_xor_sync(0xffffffffu, s, off);
        q += __shfl_xor_sync(0xffffffffu, q, off);
    }
    float mu = s * (1.f / 250.f);
    float rs = rsqrtf(q * (1.f / 250.f) - mu * mu + 1e-5f);

    uint4 hw, lw;
    __nv_bfloat16* hp = (__nv_bfloat16*)&hw;
    __nv_bfloat16* lp = (__nv_bfloat16*)&lw;
#pragma unroll
    for (int e = 0; e < 8; e++) {
        int c = c0 + e;
        float w = (c < 250) ? (v[e] - mu) * rs * gamma[c] + beta[c] : 0.f;
        __nv_bfloat16 h = __float2bfloat16(w);
        hp[e] = h;
        lp[e] = __float2bfloat16(w - __bfloat162float(h));
    }
    *(uint4*)(ch + (size_t)r * 256 + c0) = hw;
    *(uint4*)(cl + (size_t)r * 256 + c0) = lw;
}

extern "C" void kernel_launch(void* const* d_in, const int* in_sizes, int n_in,
                              void* d_out, int out_size)
{
    const float* x       = (const float*)d_in[0];
    const float* state   = (const float*)d_in[1];
    const float* enc_W   = (const float*)d_in[2];
    const float* enc_b   = (const float*)d_in[3];
    const float* enc_g   = (const float*)d_in[4];
    const float* enc_bt  = (const float*)d_in[5];
    const float* core_W  = (const float*)d_in[6];
    const float* core_b  = (const float*)d_in[7];
    const float* core_g  = (const float*)d_in[8];
    const float* core_bt = (const float*)d_in[9];
    const float* ctx_W   = (const float*)d_in[10];
    const float* ctx_b   = (const float*)d_in[11];
    const float* ctx_g   = (const float*)d_in[12];
    const float* ctx_bt  = (const float*)d_in[13];
    const float* att_W1  = (const float*)d_in[14];
    const float* att_b1  = (const float*)d_in[15];
    const float* att_g   = (const float*)d_in[16];
    const float* att_bt  = (const float*)d_in[17];
    const float* att_W2  = (const float*)d_in[18];
    const float* att_b2  = (const float*)d_in[19];
    const float* out_W   = (const float*)d_in[20];
    const float* out_b   = (const float*)d_in[21];
    float* out = (float*)d_out;

    __nv_bfloat16 *sp_h, *sp_l, *xp_h, *xp_l, *s1_h, *s1_l, *co_h, *co_l;
    __nv_bfloat16 *ef_h, *ef_l, *eW, *uvW, *fW, *oW;
    float *uv, *eff32, *epi;
    cudaGetSymbolAddress((void**)&sp_h, g_sp_h); cudaGetSymbolAddress((void**)&sp_l, g_sp_l);
    cudaGetSymbolAddress((void**)&xp_h, g_xp_h); cudaGetSymbolAddress((void**)&xp_l, g_xp_l);
    cudaGetSymbolAddress((void**)&s1_h, g_s1_h); cudaGetSymbolAddress((void**)&s1_l, g_s1_l);
    cudaGetSymbolAddress((void**)&co_h, g_co_h); cudaGetSymbolAddress((void**)&co_l, g_co_l);
    cudaGetSymbolAddress((void**)&ef_h, g_ef_h); cudaGetSymbolAddress((void**)&ef_l, g_ef_l);
    cudaGetSymbolAddress((void**)&eW, g_eW);     cudaGetSymbolAddress((void**)&uvW, g_uvW);
    cudaGetSymbolAddress((void**)&fW, g_fW);     cudaGetSymbolAddress((void**)&oW, g_oW);
    cudaGetSymbolAddress((void**)&uv, g_uv);     cudaGetSymbolAddress((void**)&eff32, g_eff32);
    cudaGetSymbolAddress((void**)&epi, g_epi);

    const int SM_STD = 2 * (64 + 256) * 72 * 2 + 4 * 64 * 4 * 4 + 64 * 4;   // ~96.5KB
    const int SM_FUS = 2 * (64 + 384) * 72 * 2 + 4 * 64 * 4 * 4 + 64 * 4;   // ~133.5KB
    cudaFuncSetAttribute((const void*)hgemm<64, 256, 768, 0, 1>,  cudaFuncAttributeMaxDynamicSharedMemorySize, SM_STD);
    cudaFuncSetAttribute((const void*)hgemm<64, 256, 768, 0, 0>,  cudaFuncAttributeMaxDynamicSharedMemorySize, SM_STD);
    cudaFuncSetAttribute((const void*)hgemm<64, 384, 768, 0, 3>,  cudaFuncAttributeMaxDynamicSharedMemorySize, SM_FUS);
    cudaFuncSetAttribute((const void*)hgemm<64, 256, 3264, 2, 0>, cudaFuncAttributeMaxDynamicSharedMemorySize, SM_STD);

    // prep
    cvt_pad<<<(16384 * 256) / 256, 256>>>(sp_h, sp_l, 256, state, 250, 16384);
    cvt_pad<<<(16384 * 576) / 256, 256>>>(xp_h, xp_l, 576, x, 576, 16384);
    prep_w<<<(256 * 768) / 256, 256>>>(eW, 768, 256, 256, enc_W, 250, 0, 250, 0, 0, 0, 0);
    prep_w<<<(256 * 768) / 256, 256>>>(uvW,             768, 256, 256, core_W, 250, 0,   250, 0, 0, 0, 0);
    prep_w<<<(256 * 768) / 256, 256>>>(uvW + 256 * 768, 768, 256, 256, core_W, 250, 250, 250, 0, 0, 0, 0);
    prep_w<<<(256 * 768) / 256, 256>>>(fW,              768, 256, 256, ctx_W,  250, 0, 250, 0, 0, 0, 0);
    prep_w<<<(128 * 768) / 256, 256>>>(fW + 256 * 768,  768, 256, 128, att_W1, 100, 0, 250, 0, 0, 0, 0);
    epi_pack<<<2, 256>>>(epi, ctx_b, ctx_g, ctx_bt, att_b1, att_g, att_bt, att_W2);
    prep_w<<<(256 * 3264) / 256, 256>>>(oW, 3264, 1088, 256, out_W, 250, 0, 250, 250, 250, 500, 576);
    cudaMemsetAsync(eff32, 0, (size_t)16384 * 256 * sizeof(float));

    // 1. enc: s1 = LN(relu(state @ enc_W + b))
    hgemm<64, 256, 768, 0, 1><<<BKTOT / 64, 256, SM_STD>>>(
        sp_h, sp_l, nullptr, nullptr, nullptr, nullptr, eW,
        enc_b, enc_g, enc_bt, nullptr, nullptr,
        nullptr, s1_h, s1_l, 250, 0);
    // 2. UV = s1 @ [W_top ++ W_bot]
    hgemm<64, 256, 768, 0, 0><<<dim3(BKTOT / 64, 2), 256, SM_STD>>>(
        s1_h, s1_l, nullptr, nullptr, nullptr, nullptr, uvW,
        nullptr, nullptr, nullptr, nullptr, nullptr,
        uv, nullptr, nullptr, 256, 512);
    // 3. core[b,i,j] = LN(relu(U[b,i] + V[b,j] + core_b))
    combine_core<<<RR / 8, 256>>>(uv, core_b, core_g, core_bt, co_h, co_l);
    // 4. fused ctx+att+effect: eff32 += LN(relu(core@ctxW))*sigmoid(LN(tanh(core@attW1))@W2)
    hgemm<64, 384, 768, 0, 3><<<RR / 64, 256, SM_FUS>>>(
        co_h, co_l, nullptr, nullptr, nullptr, nullptr, fW,
        epi, epi + 384, epi + 768, epi + 1152, att_b2,
        eff32, nullptr, nullptr, 384, 0);
    // 5. eff32 -> hi/lo planes
    cvt_pad<<<(16384 * 256) / 256, 256>>>(ef_h, ef_l, 256, eff32, 256, 16384);
    // 6. out: [s1 | eff | x] @ out_W + b
    hgemm<64, 256, 3264, 2, 0><<<BKTOT / 64, 256, SM_STD>>>(
        s1_h, s1_l, ef_h, ef_l, xp_h, xp_l, oW,
        out_b, nullptr, nullptr, nullptr, nullptr,
        out, nullptr, nullptr, 250, 250);
}

// round 7
// speedup vs baseline: 1.0966x; 1.0966x over previous
#include <cuda_runtime.h>
#include <cuda_bf16.h>
#include <math.h>
#include <stdint.h>

static constexpr int BKTOT = 16384;
static constexpr int RR    = 114688;

// ---------------- device-global scratch (allocation-free) ----------------
__device__ __align__(16) __nv_bfloat16 g_sp_h[16384*256], g_sp_l[16384*256];
__device__ __align__(16) __nv_bfloat16 g_xp_h[16384*576], g_xp_l[16384*576];
__device__ __align__(16) __nv_bfloat16 g_s1_h[16384*256], g_s1_l[16384*256];
__device__ __align__(16) float         g_uv  [16384*512];
__device__ __align__(16) __nv_bfloat16 g_co_h[114688*256], g_co_l[114688*256];
__device__ __align__(16) float         g_att [114688];
__device__ __align__(16) float         g_eff32[16384*256];
__device__ __align__(16) __nv_bfloat16 g_ef_h[16384*256], g_ef_l[16384*256];
__device__ __align__(16) __nv_bfloat16 g_eW [256*768];
__device__ __align__(16) __nv_bfloat16 g_uvW[512*768];
__device__ __align__(16) __nv_bfloat16 g_xW [256*768];
__device__ __align__(16) __nv_bfloat16 g_aW [128*768];
__device__ __align__(16) __nv_bfloat16 g_oW [256*3264];

// ---------------- helpers ----------------
__device__ __forceinline__ uint32_t smem_u32(const void* p) {
    uint32_t a;
    asm("{ .reg .u64 t; cvta.to.shared.u64 t, %1; cvt.u32.u64 %0, t; }" : "=r"(a) : "l"(p));
    return a;
}
__device__ __forceinline__ void cpa16(uint32_t saddr, const void* g) {
    asm volatile("cp.async.cg.shared.global [%0], [%1], 16;" :: "r"(saddr), "l"(g));
}
#define CP_COMMIT() asm volatile("cp.async.commit_group;" ::: "memory")
#define CP_WAIT(n)  asm volatile("cp.async.wait_group %0;" :: "n"(n) : "memory")

__device__ __forceinline__ void mma_bf16(float* d, const uint32_t* a, const uint32_t* b) {
    asm volatile(
        "mma.sync.aligned.m16n8k16.row.col.f32.bf16.bf16.f32 "
        "{%0,%1,%2,%3}, {%4,%5,%6,%7}, {%8,%9}, {%0,%1,%2,%3};"
        : "+f"(d[0]), "+f"(d[1]), "+f"(d[2]), "+f"(d[3])
        : "r"(a[0]), "r"(a[1]), "r"(a[2]), "r"(a[3]), "r"(b[0]), "r"(b[1]));
}
__device__ __forceinline__ float ftanh(float x) {
    float t = fminf(fmaxf(2.f * x, -30.f), 30.f);
    float e = __expf(t);
    return (e - 1.f) / (e + 1.f);
}
__device__ __forceinline__ float fsigmoid(float z) { return 1.f / (1.f + __expf(-z)); }

// ---------------- prep kernels ----------------
__global__ void cvt_pad(__nv_bfloat16* __restrict__ dh, __nv_bfloat16* __restrict__ dl,
                        int DS, const float* __restrict__ src, int SC, int rows)
{
    int idx = blockIdx.x * blockDim.x + threadIdx.x;
    if (idx >= rows * DS) return;
    int r = idx / DS, c = idx - r * DS;
    float v = (c < SC) ? src[(size_t)r * SC + c] : 0.f;
    __nv_bfloat16 h = __float2bfloat16(v);
    dh[idx] = h;
    dl[idx] = __float2bfloat16(v - __bfloat162float(h));
}

struct PrepJob {
    __nv_bfloat16* dst;
    const float*   W;
    int KTRIP, KP, N0;
    int b0, v0, b1, v1, b2, v2;
    int count;   // NP * KTRIP
};
struct PrepJobs { PrepJob j[6]; int cum[7]; };

// one full-occupancy kernel covering all weight-triple preps
__global__ void prep_all(PrepJobs J)
{
    int e = blockIdx.x * blockDim.x + threadIdx.x;
    if (e >= J.cum[6]) return;
    int ji = 0;
    while (e >= J.cum[ji + 1]) ji++;
    const PrepJob& p = J.j[ji];
    int idx = e - J.cum[ji];
    int n = idx / p.KTRIP, kk = idx - n * p.KTRIP;
    int seg = kk / p.KP, k = kk - seg * p.KP;
    bool lo = (seg == 1);
    int piece = (k >= 512) ? 2 : (k >= 256) ? 1 : 0;
    int off = k - ((piece == 2) ? 512 : piece * 256);
    int base  = (piece == 0) ? p.b0 : (piece == 1) ? p.b1 : p.b2;
    int valid = (piece == 0) ? p.v0 : (piece == 1) ? p.v1 : p.v2;
    float v = (off < valid) ? p.W[(size_t)(base + off) * p.N0 + n] : 0.f;
    if (n >= p.N0) v = 0.f;
    __nv_bfloat16 h = __float2bfloat16(v);
    if (lo) h = __float2bfloat16(v - __bfloat162float(h));
    p.dst[idx] = h;
}

// ---------------- HMMA fused GEMM ----------------
// EPI: 0 bias?+fp32 store (global-col aware); 1 relu+LN -> hi/lo planes;
//      2 tanh+LN+dot(W2)+sigmoid -> scalar; 4 relu+LN * att -> grouped eff32 accumulate
template<int BM, int BN, int KTRIP, int GATHER, int EPI>
__global__ void __launch_bounds__(256) hgemm(
    const __nv_bfloat16* __restrict__ A1h, const __nv_bfloat16* __restrict__ A1l,
    const __nv_bfloat16* __restrict__ A2h, const __nv_bfloat16* __restrict__ A2l,
    const __nv_bfloat16* __restrict__ A3h, const __nv_bfloat16* __restrict__ A3l,
    const __nv_bfloat16* __restrict__ Bw,
    const float* __restrict__ bias, const float* __restrict__ gamma, const float* __restrict__ beta,
    const float* __restrict__ W2, const float* __restrict__ b2,   // EPI4: W2 = att scores
    float* __restrict__ Cf, __nv_bfloat16* __restrict__ Chi, __nv_bfloat16* __restrict__ Clo,
    int N, int cstride)
{
    constexpr int PADK = 72;
    constexpr int NWM = BM / 32;
    constexpr int NWN = 8 / NWM;
    constexpr int NI  = BN / (8 * NWN);
    constexpr int NST = KTRIP / 64;

    extern __shared__ __align__(16) __nv_bfloat16 sm[];
    __nv_bfloat16* const Asm = sm;
    __nv_bfloat16* const Bsm = sm + 2 * BM * PADK;
    float* const red0 = (float*)(sm + 2 * (BM + BN) * PADK);
    float* const red1 = red0 + BM * NWN;
    float* const attS = red1 + 3 * BM * NWN;   // BM floats (past red region)
    const uint32_t smb = smem_u32(sm);

    const int tid = threadIdx.x, w = tid >> 5, lane = tid & 31;
    const int g = lane >> 2, tq = lane & 3;
    const int wm = w % NWM, wn = w / NWM;
    const int row0 = blockIdx.x * BM;
    const int col0 = blockIdx.y * BN;
    Bw += (size_t)col0 * KTRIP;

    float acc[2][NI][4];
#pragma unroll
    for (int mi = 0; mi < 2; mi++)
#pragma unroll
        for (int ni = 0; ni < NI; ni++)
#pragma unroll
            for (int e = 0; e < 4; e++) acc[mi][ni][e] = 0.f;

    auto gatherA = [&](int gr, int kk) -> const __nv_bfloat16* {
        if (GATHER == 0) {
            int seg = kk >> 8, k = kk & 255;
            return ((seg == 2) ? A1l : A1h) + (size_t)gr * 256 + k;
        } else {
            int seg = kk / 1088, k = kk - seg * 1088;
            bool lo = (seg == 2);
            if (k < 256) return (lo ? A1l : A1h) + (size_t)gr * 256 + k;
            if (k < 512) return (lo ? A2l : A2h) + (size_t)gr * 256 + (k - 256);
            return (lo ? A3l : A3h) + (size_t)gr * 576 + (k - 512);
        }
    };

    auto loadStage = [&](int t, int st) {
        int kb = t * 64;
#pragma unroll
        for (int u = tid; u < BM * 8; u += 256) {
            int r = u >> 3, cq = u & 7;
            cpa16(smb + (((st * BM + r) * PADK + cq * 8) << 1), gatherA(row0 + r, kb + cq * 8));
        }
#pragma unroll
        for (int u = tid; u < BN * 8; u += 256) {
            int r = u >> 3, cq = u & 7;
            cpa16(smb + ((2 * BM * PADK + (st * BN + r) * PADK + cq * 8) << 1),
                  Bw + (size_t)r * KTRIP + kb + cq * 8);
        }
    };

    auto compute = [&](int st) {
        const __nv_bfloat16* At = Asm + st * BM * PADK;
        const __nv_bfloat16* Bt = Bsm + st * BN * PADK;
#pragma unroll
        for (int kk = 0; kk < 4; kk++) {
            uint32_t a[2][4], b[NI][2];
            const int k = kk * 16 + tq * 2;
#pragma unroll
            for (int mi = 0; mi < 2; mi++) {
                int r = wm * 32 + mi * 16 + g;
                a[mi][0] = *(const uint32_t*)(At + r * PADK + k);
                a[mi][1] = *(const uint32_t*)(At + (r + 8) * PADK + k);
                a[mi][2] = *(const uint32_t*)(At + r * PADK + k + 8);
                a[mi][3] = *(const uint32_t*)(At + (r + 8) * PADK + k + 8);
            }
#pragma unroll
            for (int ni = 0; ni < NI; ni++) {
                int r = wn * (NI * 8) + ni * 8 + g;
                b[ni][0] = *(const uint32_t*)(Bt + r * PADK + k);
                b[ni][1] = *(const uint32_t*)(Bt + r * PADK + k + 8);
            }
#pragma unroll
            for (int mi = 0; mi < 2; mi++)
#pragma unroll
                for (int ni = 0; ni < NI; ni++)
                    mma_bf16(acc[mi][ni], a[mi], b[ni]);
        }
    };

    loadStage(0, 0);
    CP_COMMIT();
    for (int t = 0; t < NST; t++) {
        if (t + 1 < NST) {
            loadStage(t + 1, (t + 1) & 1);
            CP_COMMIT();
            CP_WAIT(1);
        } else {
            CP_WAIT(0);
        }
        __syncthreads();
        compute(t & 1);
        __syncthreads();
    }

    // ---------------- epilogues ----------------
    if (EPI == 0) {
#pragma unroll
        for (int mi = 0; mi < 2; mi++) {
            int r0 = row0 + wm * 32 + mi * 16 + g;
#pragma unroll
            for (int ni = 0; ni < NI; ni++) {
                int gc0 = col0 + wn * (NI * 8) + ni * 8 + tq * 2, gc1 = gc0 + 1;
                if (gc0 < N) {
                    float bv = bias ? bias[gc0] : 0.f;
                    Cf[(size_t)r0 * cstride + gc0]       = acc[mi][ni][0] + bv;
                    Cf[(size_t)(r0 + 8) * cstride + gc0] = acc[mi][ni][2] + bv;
                }
                if (gc1 < N) {
                    float bv = bias ? bias[gc1] : 0.f;
                    Cf[(size_t)r0 * cstride + gc1]       = acc[mi][ni][1] + bv;
                    Cf[(size_t)(r0 + 8) * cstride + gc1] = acc[mi][ni][3] + bv;
                }
            }
        }
        return;
    }

    // Shared stat phase for EPI 1/2/4: bias+activation, zero pads, row sums
    {
        float s[2][2] = {{0,0},{0,0}}, q[2][2] = {{0,0},{0,0}};
#pragma unroll
        for (int mi = 0; mi < 2; mi++)
#pragma unroll
            for (int ni = 0; ni < NI; ni++) {
                int c0 = wn * (NI * 8) + ni * 8 + tq * 2, c1 = c0 + 1;
                float b0v = (c0 < N) ? bias[c0] : 0.f;
                float b1v = (c1 < N) ? bias[c1] : 0.f;
                float v0 = acc[mi][ni][0] + b0v, v1 = acc[mi][ni][1] + b1v;
                float v2 = acc[mi][ni][2] + b0v, v3 = acc[mi][ni][3] + b1v;
                if (EPI == 2) {
                    v0 = ftanh(v0); v1 = ftanh(v1); v2 = ftanh(v2); v3 = ftanh(v3);
                } else {
                    v0 = fmaxf(v0, 0.f); v1 = fmaxf(v1, 0.f);
                    v2 = fmaxf(v2, 0.f); v3 = fmaxf(v3, 0.f);
                }
                if (c0 >= N) { v0 = 0.f; v2 = 0.f; }
                if (c1 >= N) { v1 = 0.f; v3 = 0.f; }
                acc[mi][ni][0] = v0; acc[mi][ni][1] = v1;
                acc[mi][ni][2] = v2; acc[mi][ni][3] = v3;
                s[mi][0] += v0 + v1; q[mi][0] += v0 * v0 + v1 * v1;
                s[mi][1] += v2 + v3; q[mi][1] += v2 * v2 + v3 * v3;
            }
#pragma unroll
        for (int off = 1; off <= 2; off <<= 1)
#pragma unroll
            for (int mi = 0; mi < 2; mi++)
#pragma unroll
                for (int dr = 0; dr < 2; dr++) {
                    s[mi][dr] += __shfl_xor_sync(0xffffffffu, s[mi][dr], off);
                    q[mi][dr] += __shfl_xor_sync(0xffffffffu, q[mi][dr], off);
                }
        if (tq == 0)
#pragma unroll
            for (int mi = 0; mi < 2; mi++)
#pragma unroll
                for (int dr = 0; dr < 2; dr++) {
                    int r = wm * 32 + mi * 16 + g + 8 * dr;
                    red0[r * NWN + wn] = s[mi][dr];
                    red1[r * NWN + wn] = q[mi][dr];
                }
        __syncthreads();
        float mu[2][2], rs[2][2];
        const float invN = 1.f / (float)N;
#pragma unroll
        for (int mi = 0; mi < 2; mi++)
#pragma unroll
            for (int dr = 0; dr < 2; dr++) {
                int r = wm * 32 + mi * 16 + g + 8 * dr;
                float ss = 0.f, qq = 0.f;
#pragma unroll
                for (int xx = 0; xx < NWN; xx++) { ss += red0[r * NWN + xx]; qq += red1[r * NWN + xx]; }
                mu[mi][dr] = ss * invN;
                rs[mi][dr] = rsqrtf(qq * invN - mu[mi][dr] * mu[mi][dr] + 1e-5f);
            }

        if (EPI == 1) {
#pragma unroll
            for (int mi = 0; mi < 2; mi++) {
                int gr0 = row0 + wm * 32 + mi * 16 + g;
#pragma unroll
                for (int ni = 0; ni < NI; ni++) {
                    int c0 = wn * (NI * 8) + ni * 8 + tq * 2, c1 = c0 + 1;
                    float g0 = (c0 < N) ? gamma[c0] : 0.f, g1 = (c1 < N) ? gamma[c1] : 0.f;
                    float t0 = (c0 < N) ? beta[c0] : 0.f,  t1 = (c1 < N) ? beta[c1]  : 0.f;
#pragma unroll
                    for (int dr = 0; dr < 2; dr++) {
                        int gr = gr0 + 8 * dr;
                        float w0 = (c0 < N) ? (acc[mi][ni][2*dr+0] - mu[mi][dr]) * rs[mi][dr] * g0 + t0 : 0.f;
                        float w1 = (c1 < N) ? (acc[mi][ni][2*dr+1] - mu[mi][dr]) * rs[mi][dr] * g1 + t1 : 0.f;
                        __nv_bfloat16 h0 = __float2bfloat16(w0), h1 = __float2bfloat16(w1);
                        __nv_bfloat16 l0 = __float2bfloat16(w0 - __bfloat162float(h0));
                        __nv_bfloat16 l1 = __float2bfloat16(w1 - __bfloat162float(h1));
                        *(__nv_bfloat162*)(Chi + (size_t)gr * 256 + c0) = __halves2bfloat162(h0, h1);
                        *(__nv_bfloat162*)(Clo + (size_t)gr * 256 + c0) = __halves2bfloat162(l0, l1);
                    }
                }
            }
            return;
        }

        if (EPI == 2) {
            float d[2][2] = {{0,0},{0,0}};
#pragma unroll
            for (int mi = 0; mi < 2; mi++)
#pragma unroll
                for (int ni = 0; ni < NI; ni++) {
                    int c0 = wn * (NI * 8) + ni * 8 + tq * 2, c1 = c0 + 1;
#pragma unroll
                    for (int dr = 0; dr < 2; dr++) {
                        if (c0 < N)
                            d[mi][dr] += ((acc[mi][ni][2*dr+0] - mu[mi][dr]) * rs[mi][dr] * gamma[c0] + beta[c0]) * W2[c0];
                        if (c1 < N)
                            d[mi][dr] += ((acc[mi][ni][2*dr+1] - mu[mi][dr]) * rs[mi][dr] * gamma[c1] + beta[c1]) * W2[c1];
                    }
                }
#pragma unroll
            for (int off = 1; off <= 2; off <<= 1)
#pragma unroll
                for (int mi = 0; mi < 2; mi++)
#pragma unroll
                    for (int dr = 0; dr < 2; dr++)
                        d[mi][dr] += __shfl_xor_sync(0xffffffffu, d[mi][dr], off);
            __syncthreads();
            if (tq == 0)
#pragma unroll
                for (int mi = 0; mi < 2; mi++)
#pragma unroll
                    for (int dr = 0; dr < 2; dr++) {
                        int r = wm * 32 + mi * 16 + g + 8 * dr;
                        red0[r * NWN + wn] = d[mi][dr];
                    }
            __syncthreads();
            if (wn == 0 && tq == 0) {
                float bb = b2[0];
#pragma unroll
                for (int mi = 0; mi < 2; mi++)
#pragma unroll
                    for (int dr = 0; dr < 2; dr++) {
                        int r = wm * 32 + mi * 16 + g + 8 * dr;
                        float dd = 0.f;
#pragma unroll
                        for (int xx = 0; xx < NWN; xx++) dd += red0[r * NWN + xx];
                        Cf[row0 + r] = fsigmoid(dd + bb);
                    }
            }
            return;
        }

        // EPI == 4: w = LN(relu(.)); eff32[row/7] += w * att[row], grouped in smem first
        {
            const int gBase = row0 / 7;
            const int ng = (row0 + BM - 1) / 7 - gBase + 1;   // <= 10 for BM=64
            float* const grp = (float*)sm;                     // reuse A/B tiles
            if (tid < BM) attS[tid] = W2[row0 + tid];          // W2 carries att scores
            __syncthreads();
            for (int i = tid; i < ng * 256; i += 256) grp[i] = 0.f;
            __syncthreads();
#pragma unroll
            for (int mi = 0; mi < 2; mi++)
#pragma unroll
                for (int ni = 0; ni < NI; ni++) {
                    int c0 = wn * (NI * 8) + ni * 8 + tq * 2, c1 = c0 + 1;
                    if (c0 >= N) continue;
                    float g0 = gamma[c0], t0 = beta[c0];
                    float g1 = (c1 < N) ? gamma[c1] : 0.f, t1 = (c1 < N) ? beta[c1] : 0.f;
                    bool ok1 = (c1 < N);
#pragma unroll
                    for (int dr = 0; dr < 2; dr++) {
                        int rl = wm * 32 + mi * 16 + g + 8 * dr;
                        int gi = (row0 + rl) / 7 - gBase;
                        float av = attS[rl];
                        float w0 = (acc[mi][ni][2*dr+0] - mu[mi][dr]) * rs[mi][dr] * g0 + t0;
                        atomicAdd(&grp[gi * 256 + c0], w0 * av);
                        if (ok1) {
                            float w1 = (acc[mi][ni][2*dr+1] - mu[mi][dr]) * rs[mi][dr] * g1 + t1;
                            atomicAdd(&grp[gi * 256 + c1], w1 * av);
                        }
                    }
                }
            __syncthreads();
            for (int i = tid; i < ng * 256; i += 256) {
                atomicAdd(Cf + (size_t)(gBase + (i >> 8)) * 256 + (i & 255), grp[i]);
            }
        }
    }
}

// ---------------- core combine: core[b,i,j] = LN(relu(U[b,i] + V[b,j] + bias)) ----------------
__global__ void __launch_bounds__(256) combine_core(
    const float* __restrict__ UV, const float* __restrict__ bias,
    const float* __restrict__ gamma, const float* __restrict__ beta,
    __nv_bfloat16* __restrict__ ch, __nv_bfloat16* __restrict__ cl)
{
    const int r    = blockIdx.x * 8 + (threadIdx.x >> 5);
    const int lane = threadIdx.x & 31;
    const int b = r / 56, rem = r - b * 56;
    const int i = rem / 7, jj = rem - i * 7;
    const int j = jj + (jj >= i ? 1 : 0);
    const float4* up = (const float4*)(UV + (size_t)(b * 8 + i) * 512);
    const float4* vp = (const float4*)(UV + (size_t)(b * 8 + j) * 512 + 256);

    const int c0 = lane * 8;
    float v[8];
#pragma unroll
    for (int h = 0; h < 2; h++) {
        float4 u4 = up[lane * 2 + h];
        float4 v4 = vp[lane * 2 + h];
        float* vv = v + h * 4;
        vv[0] = u4.x + v4.x; vv[1] = u4.y + v4.y;
        vv[2] = u4.z + v4.z; vv[3] = u4.w + v4.w;
    }
    float s = 0.f, q = 0.f;
#pragma unroll
    for (int e = 0; e < 8; e++) {
        int c = c0 + e;
        float x = (c < 250) ? fmaxf(v[e] + bias[c], 0.f) : 0.f;
        v[e] = x;
        s += x; q += x * x;
    }
#pragma unroll
    for (int off = 16; off > 0; off >>= 1) {
        s += __shfl_xor_sync(0xffffffffu, s, off);
        q += __shfl_xor_sync(0xffffffffu, q, off);
    }
    float mu = s * (1.f / 250.f);
    float rs = rsqrtf(q * (1.f / 250.f) - mu * mu + 1e-5f);

    uint4 hw, lw;
    __nv_bfloat16* hp = (__nv_bfloat16*)&hw;
    __nv_bfloat16* lp = (__nv_bfloat16*)&lw;
#pragma unroll
    for (int e = 0; e < 8; e++) {
        int c = c0 + e;
        float w = (c < 250) ? (v[e] - mu) * rs * gamma[c] + beta[c] : 0.f;
        __nv_bfloat16 h = __float2bfloat16(w);
        hp[e] = h;
        lp[e] = __float2bfloat16(w - __bfloat162float(h));
    }
    *(uint4*)(ch + (size_t)r * 256 + c0) = hw;
    *(uint4*)(cl + (size_t)r * 256 + c0) = lw;
}

extern "C" void kernel_launch(void* const* d_in, const int* in_sizes, int n_in,
                              void* d_out, int out_size)
{
    const float* x       = (const float*)d_in[0];
    const float* state   = (const float*)d_in[1];
    const float* enc_W   = (const float*)d_in[2];
    const float* enc_b   = (const float*)d_in[3];
    const float* enc_g   = (const float*)d_in[4];
    const float* enc_bt  = (const float*)d_in[5];
    const float* core_W  = (const float*)d_in[6];
    const float* core_b  = (const float*)d_in[7];
    const float* core_g  = (const float*)d_in[8];
    const float* core_bt = (const float*)d_in[9];
    const float* ctx_W   = (const float*)d_in[10];
    const float* ctx_b   = (const float*)d_in[11];
    const float* ctx_g   = (const float*)d_in[12];
    const float* ctx_bt  = (const float*)d_in[13];
    const float* att_W1  = (const float*)d_in[14];
    const float* att_b1  = (const float*)d_in[15];
    const float* att_g   = (const float*)d_in[16];
    const float* att_bt  = (const float*)d_in[17];
    const float* att_W2  = (const float*)d_in[18];
    const float* att_b2  = (const float*)d_in[19];
    const float* out_W   = (const float*)d_in[20];
    const float* out_b   = (const float*)d_in[21];
    float* out = (float*)d_out;

    __nv_bfloat16 *sp_h, *sp_l, *xp_h, *xp_l, *s1_h, *s1_l, *co_h, *co_l;
    __nv_bfloat16 *ef_h, *ef_l, *eW, *uvW, *xW, *aW, *oW;
    float *uv, *att, *eff32;
    cudaGetSymbolAddress((void**)&sp_h, g_sp_h); cudaGetSymbolAddress((void**)&sp_l, g_sp_l);
    cudaGetSymbolAddress((void**)&xp_h, g_xp_h); cudaGetSymbolAddress((void**)&xp_l, g_xp_l);
    cudaGetSymbolAddress((void**)&s1_h, g_s1_h); cudaGetSymbolAddress((void**)&s1_l, g_s1_l);
    cudaGetSymbolAddress((void**)&co_h, g_co_h); cudaGetSymbolAddress((void**)&co_l, g_co_l);
    cudaGetSymbolAddress((void**)&ef_h, g_ef_h); cudaGetSymbolAddress((void**)&ef_l, g_ef_l);
    cudaGetSymbolAddress((void**)&eW, g_eW);     cudaGetSymbolAddress((void**)&uvW, g_uvW);
    cudaGetSymbolAddress((void**)&xW, g_xW);     cudaGetSymbolAddress((void**)&aW, g_aW);
    cudaGetSymbolAddress((void**)&oW, g_oW);     cudaGetSymbolAddress((void**)&uv, g_uv);
    cudaGetSymbolAddress((void**)&att, g_att);   cudaGetSymbolAddress((void**)&eff32, g_eff32);

    const int SM_STD = 2 * (64 + 256) * 72 * 2 + 4 * 64 * 4 * 4 + 64 * 4;    // 96512
    const int SM_ATT = 2 * (128 + 128) * 72 * 2 + 4 * 128 * 2 * 4 + 128 * 4; // 78336
    cudaFuncSetAttribute((const void*)hgemm<64, 256, 768, 0, 1>,  cudaFuncAttributeMaxDynamicSharedMemorySize, SM_STD);
    cudaFuncSetAttribute((const void*)hgemm<64, 256, 768, 0, 0>,  cudaFuncAttributeMaxDynamicSharedMemorySize, SM_STD);
    cudaFuncSetAttribute((const void*)hgemm<64, 256, 768, 0, 4>,  cudaFuncAttributeMaxDynamicSharedMemorySize, SM_STD);
    cudaFuncSetAttribute((const void*)hgemm<128, 128, 768, 0, 2>, cudaFuncAttributeMaxDynamicSharedMemorySize, SM_ATT);
    cudaFuncSetAttribute((const void*)hgemm<128, 128, 3264, 2, 0>, cudaFuncAttributeMaxDynamicSharedMemorySize, SM_ATT);

    // ---- prep ----
    cvt_pad<<<(16384 * 256) / 256, 256>>>(sp_h, sp_l, 256, state, 250, 16384);
    cvt_pad<<<(16384 * 576) / 256, 256>>>(xp_h, xp_l, 576, x, 576, 16384);

    PrepJobs J;
    auto mk = [](__nv_bfloat16* dst, const float* W, int KTRIP, int KP, int N0,
                 int b0, int v0, int b1, int v1, int b2, int v2, int NP) {
        PrepJob p; p.dst = dst; p.W = W; p.KTRIP = KTRIP; p.KP = KP; p.N0 = N0;
        p.b0 = b0; p.v0 = v0; p.b1 = b1; p.v1 = v1; p.b2 = b2; p.v2 = v2;
        p.count = NP * KTRIP; return p;
    };
    J.j[0] = mk(eW,              enc_W,  768, 256, 250, 0, 250, 0, 0, 0, 0, 256);
    J.j[1] = mk(uvW,             core_W, 768, 256, 250, 0, 250, 0, 0, 0, 0, 256);
    J.j[2] = mk(uvW + 256 * 768, core_W, 768, 256, 250, 250, 250, 0, 0, 0, 0, 256);
    J.j[3] = mk(xW,              ctx_W,  768, 256, 250, 0, 250, 0, 0, 0, 0, 256);
    J.j[4] = mk(aW,              att_W1, 768, 256, 100, 0, 250, 0, 0, 0, 0, 128);
    J.j[5] = mk(oW,              out_W,  3264, 1088, 250, 0, 250, 250, 250, 500, 576, 256);
    J.cum[0] = 0;
    for (int i = 0; i < 6; i++) J.cum[i + 1] = J.cum[i] + J.j[i].count;
    prep_all<<<(J.cum[6] + 255) / 256, 256>>>(J);
    cudaMemsetAsync(eff32, 0, (size_t)16384 * 256 * sizeof(float));

    // 1. enc: s1 = LN(relu(state @ enc_W + b))
    hgemm<64, 256, 768, 0, 1><<<BKTOT / 64, 256, SM_STD>>>(
        sp_h, sp_l, nullptr, nullptr, nullptr, nullptr, eW,
        enc_b, enc_g, enc_bt, nullptr, nullptr,
        nullptr, s1_h, s1_l, 250, 0);
    // 2. UV = s1 @ [W_top ++ W_bot]
    hgemm<64, 256, 768, 0, 0><<<dim3(BKTOT / 64, 2), 256, SM_STD>>>(
        s1_h, s1_l, nullptr, nullptr, nullptr, nullptr, uvW,
        nullptr, nullptr, nullptr, nullptr, nullptr,
        uv, nullptr, nullptr, 512, 512);
    // 3. core[b,i,j] = LN(relu(U[b,i] + V[b,j] + core_b))
    combine_core<<<RR / 8, 256>>>(uv, core_b, core_g, core_bt, co_h, co_l);
    // 4. att scores (must precede fused ctx)
    hgemm<128, 128, 768, 0, 2><<<RR / 128, 256, SM_ATT>>>(
        co_h, co_l, nullptr, nullptr, nullptr, nullptr, aW,
        att_b1, att_g, att_bt, att_W2, att_b2,
        att, nullptr, nullptr, 100, 0);
    // 5. fused ctx + effect: eff32[bk] += LN(relu(core @ ctx_W)) * att
    hgemm<64, 256, 768, 0, 4><<<RR / 64, 256, SM_STD>>>(
        co_h, co_l, nullptr, nullptr, nullptr, nullptr, xW,
        ctx_b, ctx_g, ctx_bt, att, nullptr,
        eff32, nullptr, nullptr, 250, 0);
    // 6. eff32 -> hi/lo planes
    cvt_pad<<<(16384 * 256) / 256, 256>>>(ef_h, ef_l, 256, eff32, 256, 16384);
    // 7. out: [s1 | eff | x] @ out_W + b
    hgemm<128, 128, 3264, 2, 0><<<dim3(BKTOT / 128, 2), 256, SM_ATT>>>(
        s1_h, s1_l, ef_h, ef_l, xp_h, xp_l, oW,
        out_b, nullptr, nullptr, nullptr, nullptr,
        out, nullptr, nullptr, 250, 250);
}

// round 10
// speedup vs baseline: 1.1149x; 1.0167x over previous
#include <cuda_runtime.h>
#include <cuda_bf16.h>
#include <math.h>
#include <stdint.h>

static constexpr int BKTOT = 16384;
static constexpr int RR    = 114688;

// ---------------- device-global scratch (allocation-free) ----------------
__device__ __align__(16) __nv_bfloat16 g_sp_h[16384*256], g_sp_l[16384*256];
__device__ __align__(16) __nv_bfloat16 g_xp_h[16384*576], g_xp_l[16384*576];
__device__ __align__(16) __nv_bfloat16 g_s1_h[16384*256], g_s1_l[16384*256];
__device__ __align__(16) float         g_uv  [16384*512];
__device__ __align__(16) __nv_bfloat16 g_co_h[114688*256], g_co_l[114688*256];
__device__ __align__(16) __nv_bfloat16 g_cx_h[114688*256], g_cx_l[114688*256];
__device__ __align__(16) float         g_att [114688];
__device__ __align__(16) __nv_bfloat16 g_ef_h[16384*256], g_ef_l[16384*256];
__device__ __align__(16) __nv_bfloat16 g_eW [256*768];
__device__ __align__(16) __nv_bfloat16 g_uvW[512*768];
__device__ __align__(16) __nv_bfloat16 g_xW [256*768];
__device__ __align__(16) __nv_bfloat16 g_aW [128*768];
__device__ __align__(16) __nv_bfloat16 g_oW [256*3264];

// ---------------- helpers ----------------
__device__ __forceinline__ uint32_t smem_u32(const void* p) {
    uint32_t a;
    asm("{ .reg .u64 t; cvta.to.shared.u64 t, %1; cvt.u32.u64 %0, t; }" : "=r"(a) : "l"(p));
    return a;
}
__device__ __forceinline__ void cpa16(uint32_t saddr, const void* g) {
    asm volatile("cp.async.cg.shared.global [%0], [%1], 16;" :: "r"(saddr), "l"(g));
}
#define CP_COMMIT() asm volatile("cp.async.commit_group;" ::: "memory")
#define CP_WAIT(n)  asm volatile("cp.async.wait_group %0;" :: "n"(n) : "memory")

__device__ __forceinline__ void mma_bf16(float* d, const uint32_t* a, const uint32_t* b) {
    asm volatile(
        "mma.sync.aligned.m16n8k16.row.col.f32.bf16.bf16.f32 "
        "{%0,%1,%2,%3}, {%4,%5,%6,%7}, {%8,%9}, {%0,%1,%2,%3};"
        : "+f"(d[0]), "+f"(d[1]), "+f"(d[2]), "+f"(d[3])
        : "r"(a[0]), "r"(a[1]), "r"(a[2]), "r"(a[3]), "r"(b[0]), "r"(b[1]));
}
__device__ __forceinline__ float ftanh(float x) {
    float t = fminf(fmaxf(2.f * x, -30.f), 30.f);
    float e = __expf(t);
    return (e - 1.f) / (e + 1.f);
}
__device__ __forceinline__ float fsigmoid(float z) { return 1.f / (1.f + __expf(-z)); }

// ---------------- prep kernels ----------------
__global__ void cvt_pad(__nv_bfloat16* __restrict__ dh, __nv_bfloat16* __restrict__ dl,
                        int DS, const float* __restrict__ src, int SC, int rows)
{
    int idx = blockIdx.x * blockDim.x + threadIdx.x;
    if (idx >= rows * DS) return;
    int r = idx / DS, c = idx - r * DS;
    float v = (c < SC) ? src[(size_t)r * SC + c] : 0.f;
    __nv_bfloat16 h = __float2bfloat16(v);
    dh[idx] = h;
    dl[idx] = __float2bfloat16(v - __bfloat162float(h));
}

struct PrepJob {
    __nv_bfloat16* dst;
    const float*   W;
    int KTRIP, KP, N0;
    int b0, v0, b1, v1, b2, v2;
    int count;
};
struct PrepJobs { PrepJob j[6]; int cum[7]; };

__global__ void prep_all(PrepJobs J)
{
    int e = blockIdx.x * blockDim.x + threadIdx.x;
    if (e >= J.cum[6]) return;
    int ji = 0;
    while (e >= J.cum[ji + 1]) ji++;
    const PrepJob& p = J.j[ji];
    int idx = e - J.cum[ji];
    int n = idx / p.KTRIP, kk = idx - n * p.KTRIP;
    int seg = kk / p.KP, k = kk - seg * p.KP;
    bool lo = (seg == 1);
    int piece = (k >= 512) ? 2 : (k >= 256) ? 1 : 0;
    int off = k - ((piece == 2) ? 512 : piece * 256);
    int base  = (piece == 0) ? p.b0 : (piece == 1) ? p.b1 : p.b2;
    int valid = (piece == 0) ? p.v0 : (piece == 1) ? p.v1 : p.v2;
    float v = (off < valid && n < p.N0) ? p.W[(size_t)(base + off) * p.N0 + n] : 0.f;
    __nv_bfloat16 h = __float2bfloat16(v);
    if (lo) h = __float2bfloat16(v - __bfloat162float(h));
    p.dst[idx] = h;
}

// ---------------- HMMA fused GEMM: 3-stage cp.async pipeline, BK=32, 1 sync/stage ----
// EPI: 0 bias?+fp32 store (global cols); 1 relu+LN -> hi/lo planes; 2 tanh+LN+dot(W2)+sigmoid
template<int BM, int BN, int KTRIP, int GATHER, int EPI>
__global__ void __launch_bounds__(256, 2) hgemm(
    const __nv_bfloat16* __restrict__ A1h, const __nv_bfloat16* __restrict__ A1l,
    const __nv_bfloat16* __restrict__ A2h, const __nv_bfloat16* __restrict__ A2l,
    const __nv_bfloat16* __restrict__ A3h, const __nv_bfloat16* __restrict__ A3l,
    const __nv_bfloat16* __restrict__ Bw,
    const float* __restrict__ bias, const float* __restrict__ gamma, const float* __restrict__ beta,
    const float* __restrict__ W2, const float* __restrict__ b2,
    float* __restrict__ Cf, __nv_bfloat16* __restrict__ Chi, __nv_bfloat16* __restrict__ Clo,
    int N, int cstride)
{
    constexpr int PADK = 40;                  // halves per 32-half stage row (20 words)
    constexpr int NWM = BM / 32;
    constexpr int NWN = 8 / NWM;
    constexpr int NI  = BN / (8 * NWN);
    constexpr int NST = KTRIP / 32;

    extern __shared__ __align__(16) __nv_bfloat16 sm[];
    __nv_bfloat16* const Asm = sm;
    __nv_bfloat16* const Bsm = sm + 3 * BM * PADK;
    float* const red0 = (float*)(sm + 3 * (BM + BN) * PADK);
    float* const red1 = red0 + BM * NWN;
    const uint32_t smb = smem_u32(sm);

    const int tid = threadIdx.x, w = tid >> 5, lane = tid & 31;
    const int g = lane >> 2, tq = lane & 3;
    const int wm = w % NWM, wn = w / NWM;
    const int row0 = blockIdx.x * BM;
    const int col0 = blockIdx.y * BN;
    Bw += (size_t)col0 * KTRIP;

    float acc[2][NI][4];
#pragma unroll
    for (int mi = 0; mi < 2; mi++)
#pragma unroll
        for (int ni = 0; ni < NI; ni++)
#pragma unroll
            for (int e = 0; e < 4; e++) acc[mi][ni][e] = 0.f;

    auto gatherA = [&](int gr, int kk) -> const __nv_bfloat16* {
        if (GATHER == 0) {
            int seg = kk >> 8, k = kk & 255;
            return ((seg == 2) ? A1l : A1h) + (size_t)gr * 256 + k;
        } else {
            int seg = kk / 1088, k = kk - seg * 1088;
            bool lo = (seg == 2);
            if (k < 256) return (lo ? A1l : A1h) + (size_t)gr * 256 + k;
            if (k < 512) return (lo ? A2l : A2h) + (size_t)gr * 256 + (k - 256);
            return (lo ? A3l : A3h) + (size_t)gr * 576 + (k - 512);
        }
    };

    auto loadStage = [&](int t, int st) {
        int kb = t * 32;
#pragma unroll
        for (int u = tid; u < BM * 4; u += 256) {
            int r = u >> 2, cq = u & 3;
            cpa16(smb + (((st * BM + r) * PADK + cq * 8) << 1), gatherA(row0 + r, kb + cq * 8));
        }
#pragma unroll
        for (int u = tid; u < BN * 4; u += 256) {
            int r = u >> 2, cq = u & 3;
            cpa16(smb + ((3 * BM * PADK + (st * BN + r) * PADK + cq * 8) << 1),
                  Bw + (size_t)r * KTRIP + kb + cq * 8);
        }
    };

    auto compute = [&](int st) {
        const __nv_bfloat16* At = Asm + st * BM * PADK;
        const __nv_bfloat16* Bt = Bsm + st * BN * PADK;
#pragma unroll
        for (int kk = 0; kk < 2; kk++) {
            uint32_t a[2][4], b[NI][2];
            const int k = kk * 16 + tq * 2;
#pragma unroll
            for (int mi = 0; mi < 2; mi++) {
                int r = wm * 32 + mi * 16 + g;
                a[mi][0] = *(const uint32_t*)(At + r * PADK + k);
                a[mi][1] = *(const uint32_t*)(At + (r + 8) * PADK + k);
                a[mi][2] = *(const uint32_t*)(At + r * PADK + k + 8);
                a[mi][3] = *(const uint32_t*)(At + (r + 8) * PADK + k + 8);
            }
#pragma unroll
            for (int ni = 0; ni < NI; ni++) {
                int r = wn * (NI * 8) + ni * 8 + g;
                b[ni][0] = *(const uint32_t*)(Bt + r * PADK + k);
                b[ni][1] = *(const uint32_t*)(Bt + r * PADK + k + 8);
            }
#pragma unroll
            for (int mi = 0; mi < 2; mi++)
#pragma unroll
                for (int ni = 0; ni < NI; ni++)
                    mma_bf16(acc[mi][ni], a[mi], b[ni]);
        }
    };

    // 3-stage pipeline, ONE barrier per stage. Tail must drain ALL groups.
    loadStage(0, 0); CP_COMMIT();
    loadStage(1, 1); CP_COMMIT();
    for (int t = 0; t < NST; t++) {
        if (t + 1 < NST) { CP_WAIT(1); } else { CP_WAIT(0); }  // ensure stage t landed
        __syncthreads();       // all warps done with compute(t-1) -> buffer (t+2)%3 free
        if (t + 2 < NST) { loadStage(t + 2, (t + 2) % 3); CP_COMMIT(); }
        compute(t % 3);
    }

    // ---------------- epilogues ----------------
    if (EPI == 0) {
#pragma unroll
        for (int mi = 0; mi < 2; mi++) {
            int r0 = row0 + wm * 32 + mi * 16 + g;
#pragma unroll
            for (int ni = 0; ni < NI; ni++) {
                int gc0 = col0 + wn * (NI * 8) + ni * 8 + tq * 2, gc1 = gc0 + 1;
                if (gc0 < N) {
                    float bv = bias ? bias[gc0] : 0.f;
                    Cf[(size_t)r0 * cstride + gc0]       = acc[mi][ni][0] + bv;
                    Cf[(size_t)(r0 + 8) * cstride + gc0] = acc[mi][ni][2] + bv;
                }
                if (gc1 < N) {
                    float bv = bias ? bias[gc1] : 0.f;
                    Cf[(size_t)r0 * cstride + gc1]       = acc[mi][ni][1] + bv;
                    Cf[(size_t)(r0 + 8) * cstride + gc1] = acc[mi][ni][3] + bv;
                }
            }
        }
        return;
    }

    // stat phase (EPI 1/2)
    float s[2][2] = {{0,0},{0,0}}, q[2][2] = {{0,0},{0,0}};
#pragma unroll
    for (int mi = 0; mi < 2; mi++)
#pragma unroll
        for (int ni = 0; ni < NI; ni++) {
            int c0 = wn * (NI * 8) + ni * 8 + tq * 2, c1 = c0 + 1;
            float b0v = (c0 < N) ? bias[c0] : 0.f;
            float b1v = (c1 < N) ? bias[c1] : 0.f;
            float v0 = acc[mi][ni][0] + b0v, v1 = acc[mi][ni][1] + b1v;
            float v2 = acc[mi][ni][2] + b0v, v3 = acc[mi][ni][3] + b1v;
            if (EPI == 2) {
                v0 = ftanh(v0); v1 = ftanh(v1); v2 = ftanh(v2); v3 = ftanh(v3);
            } else {
                v0 = fmaxf(v0, 0.f); v1 = fmaxf(v1, 0.f);
                v2 = fmaxf(v2, 0.f); v3 = fmaxf(v3, 0.f);
            }
            if (c0 >= N) { v0 = 0.f; v2 = 0.f; }
            if (c1 >= N) { v1 = 0.f; v3 = 0.f; }
            acc[mi][ni][0] = v0; acc[mi][ni][1] = v1;
            acc[mi][ni][2] = v2; acc[mi][ni][3] = v3;
            s[mi][0] += v0 + v1; q[mi][0] += v0 * v0 + v1 * v1;
            s[mi][1] += v2 + v3; q[mi][1] += v2 * v2 + v3 * v3;
        }
#pragma unroll
    for (int off = 1; off <= 2; off <<= 1)
#pragma unroll
        for (int mi = 0; mi < 2; mi++)
#pragma unroll
            for (int dr = 0; dr < 2; dr++) {
                s[mi][dr] += __shfl_xor_sync(0xffffffffu, s[mi][dr], off);
                q[mi][dr] += __shfl_xor_sync(0xffffffffu, q[mi][dr], off);
            }
    __syncthreads();
    if (tq == 0)
#pragma unroll
        for (int mi = 0; mi < 2; mi++)
#pragma unroll
            for (int dr = 0; dr < 2; dr++) {
                int r = wm * 32 + mi * 16 + g + 8 * dr;
                red0[r * NWN + wn] = s[mi][dr];
                red1[r * NWN + wn] = q[mi][dr];
            }
    __syncthreads();
    float mu[2][2], rs[2][2];
    const float invN = 1.f / (float)N;
#pragma unroll
    for (int mi = 0; mi < 2; mi++)
#pragma unroll
        for (int dr = 0; dr < 2; dr++) {
            int r = wm * 32 + mi * 16 + g + 8 * dr;
            float ss = 0.f, qq = 0.f;
#pragma unroll
            for (int xx = 0; xx < NWN; xx++) { ss += red0[r * NWN + xx]; qq += red1[r * NWN + xx]; }
            mu[mi][dr] = ss * invN;
            rs[mi][dr] = rsqrtf(qq * invN - mu[mi][dr] * mu[mi][dr] + 1e-5f);
        }

    if (EPI == 1) {
#pragma unroll
        for (int mi = 0; mi < 2; mi++) {
            int gr0 = row0 + wm * 32 + mi * 16 + g;
#pragma unroll
            for (int ni = 0; ni < NI; ni++) {
                int c0 = wn * (NI * 8) + ni * 8 + tq * 2, c1 = c0 + 1;
                float g0 = (c0 < N) ? gamma[c0] : 0.f, g1 = (c1 < N) ? gamma[c1] : 0.f;
                float t0 = (c0 < N) ? beta[c0] : 0.f,  t1 = (c1 < N) ? beta[c1]  : 0.f;
#pragma unroll
                for (int dr = 0; dr < 2; dr++) {
                    int gr = gr0 + 8 * dr;
                    float w0 = (c0 < N) ? (acc[mi][ni][2*dr+0] - mu[mi][dr]) * rs[mi][dr] * g0 + t0 : 0.f;
                    float w1 = (c1 < N) ? (acc[mi][ni][2*dr+1] - mu[mi][dr]) * rs[mi][dr] * g1 + t1 : 0.f;
                    __nv_bfloat16 h0 = __float2bfloat16(w0), h1 = __float2bfloat16(w1);
                    __nv_bfloat16 l0 = __float2bfloat16(w0 - __bfloat162float(h0));
                    __nv_bfloat16 l1 = __float2bfloat16(w1 - __bfloat162float(h1));
                    *(__nv_bfloat162*)(Chi + (size_t)gr * 256 + c0) = __halves2bfloat162(h0, h1);
                    *(__nv_bfloat162*)(Clo + (size_t)gr * 256 + c0) = __halves2bfloat162(l0, l1);
                }
            }
        }
        return;
    }

    // EPI == 2
    {
        float d[2][2] = {{0,0},{0,0}};
#pragma unroll
        for (int mi = 0; mi < 2; mi++)
#pragma unroll
            for (int ni = 0; ni < NI; ni++) {
                int c0 = wn * (NI * 8) + ni * 8 + tq * 2, c1 = c0 + 1;
#pragma unroll
                for (int dr = 0; dr < 2; dr++) {
                    if (c0 < N)
                        d[mi][dr] += ((acc[mi][ni][2*dr+0] - mu[mi][dr]) * rs[mi][dr] * gamma[c0] + beta[c0]) * W2[c0];
                    if (c1 < N)
                        d[mi][dr] += ((acc[mi][ni][2*dr+1] - mu[mi][dr]) * rs[mi][dr] * gamma[c1] + beta[c1]) * W2[c1];
                }
            }
#pragma unroll
        for (int off = 1; off <= 2; off <<= 1)
#pragma unroll
            for (int mi = 0; mi < 2; mi++)
#pragma unroll
                for (int dr = 0; dr < 2; dr++)
                    d[mi][dr] += __shfl_xor_sync(0xffffffffu, d[mi][dr], off);
        __syncthreads();
        if (tq == 0)
#pragma unroll
            for (int mi = 0; mi < 2; mi++)
#pragma unroll
                for (int dr = 0; dr < 2; dr++) {
                    int r = wm * 32 + mi * 16 + g + 8 * dr;
                    red0[r * NWN + wn] = d[mi][dr];
                }
        __syncthreads();
        if (wn == 0 && tq == 0) {
            float bb = b2[0];
#pragma unroll
            for (int mi = 0; mi < 2; mi++)
#pragma unroll
                for (int dr = 0; dr < 2; dr++) {
                    int r = wm * 32 + mi * 16 + g + 8 * dr;
                    float dd = 0.f;
#pragma unroll
                    for (int xx = 0; xx < NWN; xx++) dd += red0[r * NWN + xx];
                    Cf[row0 + r] = fsigmoid(dd + bb);
                }
        }
    }
}

// ---------------- core combine ----------------
__global__ void __launch_bounds__(256) combine_core(
    const float* __restrict__ UV, const float* __restrict__ bias,
    const float* __restrict__ gamma, const float* __restrict__ beta,
    __nv_bfloat16* __restrict__ ch, __nv_bfloat16* __restrict__ cl)
{
    const int r    = blockIdx.x * 8 + (threadIdx.x >> 5);
    const int lane = threadIdx.x & 31;
    const int b = r / 56, rem = r - b * 56;
    const int i = rem / 7, jj = rem - i * 7;
    const int j = jj + (jj >= i ? 1 : 0);
    const float4* up = (const float4*)(UV + (size_t)(b * 8 + i) * 512);
    const float4* vp = (const float4*)(UV + (size_t)(b * 8 + j) * 512 + 256);

    const int c0 = lane * 8;
    float v[8];
#pragma unroll
    for (int h = 0; h < 2; h++) {
        float4 u4 = up[lane * 2 + h];
        float4 v4 = vp[lane * 2 + h];
        float* vv = v + h * 4;
        vv[0] = u4.x + v4.x; vv[1] = u4.y + v4.y;
        vv[2] = u4.z + v4.z; vv[3] = u4.w + v4.w;
    }
    float s = 0.f, q = 0.f;
#pragma unroll
    for (int e = 0; e < 8; e++) {
        int c = c0 + e;
        float x = (c < 250) ? fmaxf(v[e] + bias[c], 0.f) : 0.f;
        v[e] = x;
        s += x; q += x * x;
    }
#pragma unroll
    for (int off = 16; off > 0; off >>= 1) {
        s += __shfl_xor_sync(0xffffffffu, s, off);
        q += __shfl_xor_sync(0xffffffffu, q, off);
    }
    float mu = s * (1.f / 250.f);
    float rs = rsqrtf(q * (1.f / 250.f) - mu * mu + 1e-5f);

    uint4 hw, lw;
    __nv_bfloat16* hp = (__nv_bfloat16*)&hw;
    __nv_bfloat16* lp = (__nv_bfloat16*)&lw;
#pragma unroll
    for (int e = 0; e < 8; e++) {
        int c = c0 + e;
        float w = (c < 250) ? (v[e] - mu) * rs * gamma[c] + beta[c] : 0.f;
        __nv_bfloat16 h = __float2bfloat16(w);
        hp[e] = h;
        lp[e] = __float2bfloat16(w - __bfloat162float(h));
    }
    *(uint4*)(ch + (size_t)r * 256 + c0) = hw;
    *(uint4*)(cl + (size_t)r * 256 + c0) = lw;
}

// effect: eff[bk][c] = sum_j (ctx_hi+ctx_lo)[bk*7+j][c] * att[bk*7+j], stored hi/lo
__global__ void effect3(const __nv_bfloat16* __restrict__ ch, const __nv_bfloat16* __restrict__ cl,
                        const float* __restrict__ att,
                        __nv_bfloat16* __restrict__ eh, __nv_bfloat16* __restrict__ el)
{
    int bk = blockIdx.x, c = threadIdx.x;
    __shared__ float a[7];
    if (c < 7) a[c] = att[bk * 7 + c];
    __syncthreads();
    size_t base = (size_t)bk * 7 * 256 + c;
    float s = 0.f;
#pragma unroll
    for (int j = 0; j < 7; j++)
        s = fmaf(__bfloat162float(ch[base + j * 256]) + __bfloat162float(cl[base + j * 256]),
                 a[j], s);
    __nv_bfloat16 h = __float2bfloat16(s);
    eh[(size_t)bk * 256 + c] = h;
    el[(size_t)bk * 256 + c] = __float2bfloat16(s - __bfloat162float(h));
}

extern "C" void kernel_launch(void* const* d_in, const int* in_sizes, int n_in,
                              void* d_out, int out_size)
{
    const float* x       = (const float*)d_in[0];
    const float* state   = (const float*)d_in[1];
    const float* enc_W   = (const float*)d_in[2];
    const float* enc_b   = (const float*)d_in[3];
    const float* enc_g   = (const float*)d_in[4];
    const float* enc_bt  = (const float*)d_in[5];
    const float* core_W  = (const float*)d_in[6];
    const float* core_b  = (const float*)d_in[7];
    const float* core_g  = (const float*)d_in[8];
    const float* core_bt = (const float*)d_in[9];
    const float* ctx_W   = (const float*)d_in[10];
    const float* ctx_b   = (const float*)d_in[11];
    const float* ctx_g   = (const float*)d_in[12];
    const float* ctx_bt  = (const float*)d_in[13];
    const float* att_W1  = (const float*)d_in[14];
    const float* att_b1  = (const float*)d_in[15];
    const float* att_g   = (const float*)d_in[16];
    const float* att_bt  = (const float*)d_in[17];
    const float* att_W2  = (const float*)d_in[18];
    const float* att_b2  = (const float*)d_in[19];
    const float* out_W   = (const float*)d_in[20];
    const float* out_b   = (const float*)d_in[21];
    float* out = (float*)d_out;

    __nv_bfloat16 *sp_h, *sp_l, *xp_h, *xp_l, *s1_h, *s1_l, *co_h, *co_l, *cx_h, *cx_l;
    __nv_bfloat16 *ef_h, *ef_l, *eW, *uvW, *xW, *aW, *oW;
    float *uv, *att;
    cudaGetSymbolAddress((void**)&sp_h, g_sp_h); cudaGetSymbolAddress((void**)&sp_l, g_sp_l);
    cudaGetSymbolAddress((void**)&xp_h, g_xp_h); cudaGetSymbolAddress((void**)&xp_l, g_xp_l);
    cudaGetSymbolAddress((void**)&s1_h, g_s1_h); cudaGetSymbolAddress((void**)&s1_l, g_s1_l);
    cudaGetSymbolAddress((void**)&co_h, g_co_h); cudaGetSymbolAddress((void**)&co_l, g_co_l);
    cudaGetSymbolAddress((void**)&cx_h, g_cx_h); cudaGetSymbolAddress((void**)&cx_l, g_cx_l);
    cudaGetSymbolAddress((void**)&ef_h, g_ef_h); cudaGetSymbolAddress((void**)&ef_l, g_ef_l);
    cudaGetSymbolAddress((void**)&eW, g_eW);     cudaGetSymbolAddress((void**)&uvW, g_uvW);
    cudaGetSymbolAddress((void**)&xW, g_xW);     cudaGetSymbolAddress((void**)&aW, g_aW);
    cudaGetSymbolAddress((void**)&oW, g_oW);     cudaGetSymbolAddress((void**)&uv, g_uv);
    cudaGetSymbolAddress((void**)&att, g_att);

    const int SM_STD = 3 * (64 + 256) * 40 * 2 + 2 * 64 * 4 * 4;    // 78848
    const int SM_ATT = 3 * (128 + 128) * 40 * 2 + 2 * 128 * 2 * 4;  // 63488
    cudaFuncSetAttribute((const void*)hgemm<64, 256, 768, 0, 1>,   cudaFuncAttributeMaxDynamicSharedMemorySize, SM_STD);
    cudaFuncSetAttribute((const void*)hgemm<64, 256, 768, 0, 0>,   cudaFuncAttributeMaxDynamicSharedMemorySize, SM_STD);
    cudaFuncSetAttribute((const void*)hgemm<128, 128, 768, 0, 2>,  cudaFuncAttributeMaxDynamicSharedMemorySize, SM_ATT);
    cudaFuncSetAttribute((const void*)hgemm<64, 256, 3264, 2, 0>,  cudaFuncAttributeMaxDynamicSharedMemorySize, SM_STD);

    // ---- prep ----
    cvt_pad<<<(16384 * 256) / 256, 256>>>(sp_h, sp_l, 256, state, 250, 16384);
    cvt_pad<<<(16384 * 576) / 256, 256>>>(xp_h, xp_l, 576, x, 576, 16384);

    PrepJobs J;
    auto mk = [](__nv_bfloat16* dst, const float* W, int KTRIP, int KP, int N0,
                 int b0, int v0, int b1, int v1, int b2, int v2, int NP) {
        PrepJob p; p.dst = dst; p.W = W; p.KTRIP = KTRIP; p.KP = KP; p.N0 = N0;
        p.b0 = b0; p.v0 = v0; p.b1 = b1; p.v1 = v1; p.b2 = b2; p.v2 = v2;
        p.count = NP * KTRIP; return p;
    };
    J.j[0] = mk(eW,              enc_W,  768, 256, 250, 0, 250, 0, 0, 0, 0, 256);
    J.j[1] = mk(uvW,             core_W, 768, 256, 250, 0, 250, 0, 0, 0, 0, 256);
    J.j[2] = mk(uvW + 256 * 768, core_W, 768, 256, 250, 250, 250, 0, 0, 0, 0, 256);
    J.j[3] = mk(xW,              ctx_W,  768, 256, 250, 0, 250, 0, 0, 0, 0, 256);
    J.j[4] = mk(aW,              att_W1, 768, 256, 100, 0, 250, 0, 0, 0, 0, 128);
    J.j[5] = mk(oW,              out_W,  3264, 1088, 250, 0, 250, 250, 250, 500, 576, 256);
    J.cum[0] = 0;
    for (int i = 0; i < 6; i++) J.cum[i + 1] = J.cum[i] + J.j[i].count;
    prep_all<<<(J.cum[6] + 255) / 256, 256>>>(J);

    // 1. enc: s1 = LN(relu(state @ enc_W + b))
    hgemm<64, 256, 768, 0, 1><<<BKTOT / 64, 256, SM_STD>>>(
        sp_h, sp_l, nullptr, nullptr, nullptr, nullptr, eW,
        enc_b, enc_g, enc_bt, nullptr, nullptr,
        nullptr, s1_h, s1_l, 250, 0);
    // 2. UV = s1 @ [W_top ++ W_bot]
    hgemm<64, 256, 768, 0, 0><<<dim3(BKTOT / 64, 2), 256, SM_STD>>>(
        s1_h, s1_l, nullptr, nullptr, nullptr, nullptr, uvW,
        nullptr, nullptr, nullptr, nullptr, nullptr,
        uv, nullptr, nullptr, 512, 512);
    // 3. core[b,i,j] = LN(relu(U[b,i] + V[b,j] + core_b))
    combine_core<<<RR / 8, 256>>>(uv, core_b, core_g, core_bt, co_h, co_l);
    // 4. ctx = LN(relu(core @ ctx_W)) -> hi/lo planes
    hgemm<64, 256, 768, 0, 1><<<RR / 64, 256, SM_STD>>>(
        co_h, co_l, nullptr, nullptr, nullptr, nullptr, xW,
        ctx_b, ctx_g, ctx_bt, nullptr, nullptr,
        nullptr, cx_h, cx_l, 250, 0);
    // 5. att scores
    hgemm<128, 128, 768, 0, 2><<<RR / 128, 256, SM_ATT>>>(
        co_h, co_l, nullptr, nullptr, nullptr, nullptr, aW,
        att_b1, att_g, att_bt, att_W2, att_b2,
        att, nullptr, nullptr, 100, 0);
    // 6. attention-weighted reduction
    effect3<<<BKTOT, 256>>>(cx_h, cx_l, att, ef_h, ef_l);
    // 7. out: [s1 | eff | x] @ out_W + b
    hgemm<64, 256, 3264, 2, 0><<<BKTOT / 64, 256, SM_STD>>>(
        s1_h, s1_l, ef_h, ef_l, xp_h, xp_l, oW,
        out_b, nullptr, nullptr, nullptr, nullptr,
        out, nullptr, nullptr, 250, 250);
}

// round 11
// speedup vs baseline: 1.5896x; 1.4257x over previous
#include <cuda_runtime.h>
#include <cuda_bf16.h>
#include <math.h>
#include <stdint.h>

static constexpr int BKTOT = 16384;
static constexpr int RR    = 114688;

// ---------------- device-global scratch (allocation-free), fp32 tf32-prerounded ----
__device__ __align__(16) float g_sp [16384*256];
__device__ __align__(16) float g_xp [16384*576];
__device__ __align__(16) float g_s1 [16384*256];
__device__ __align__(16) float g_uv [16384*512];
__device__ __align__(16) float g_co [114688*256];
__device__ __align__(16) float g_cx [114688*256];
__device__ __align__(16) float g_att[114688];
__device__ __align__(16) float g_ef [16384*256];
__device__ __align__(16) float g_eW [256*256];
__device__ __align__(16) float g_uvW[512*256];
__device__ __align__(16) float g_xW [256*256];
__device__ __align__(16) float g_aW [128*256];
__device__ __align__(16) float g_oW [256*1088];

// ---------------- helpers ----------------
__device__ __forceinline__ uint32_t smem_u32(const void* p) {
    uint32_t a;
    asm("{ .reg .u64 t; cvta.to.shared.u64 t, %1; cvt.u32.u64 %0, t; }" : "=r"(a) : "l"(p));
    return a;
}
__device__ __forceinline__ void cpa16(uint32_t saddr, const void* g) {
    asm volatile("cp.async.cg.shared.global [%0], [%1], 16;" :: "r"(saddr), "l"(g));
}
#define CP_COMMIT() asm volatile("cp.async.commit_group;" ::: "memory")
#define CP_WAIT(n)  asm volatile("cp.async.wait_group %0;" :: "n"(n) : "memory")

__device__ __forceinline__ float tf32r(float x) {
    uint32_t r;
    asm("cvt.rna.tf32.f32 %0, %1;" : "=r"(r) : "f"(x));
    return __uint_as_float(r);
}
__device__ __forceinline__ void mma_tf32(float* d, const uint32_t* a, const uint32_t* b) {
    asm volatile(
        "mma.sync.aligned.m16n8k8.row.col.f32.tf32.tf32.f32 "
        "{%0,%1,%2,%3}, {%4,%5,%6,%7}, {%8,%9}, {%0,%1,%2,%3};"
        : "+f"(d[0]), "+f"(d[1]), "+f"(d[2]), "+f"(d[3])
        : "r"(a[0]), "r"(a[1]), "r"(a[2]), "r"(a[3]), "r"(b[0]), "r"(b[1]));
}
__device__ __forceinline__ float ftanh(float x) {
    float t = fminf(fmaxf(2.f * x, -30.f), 30.f);
    float e = __expf(t);
    return (e - 1.f) / (e + 1.f);
}
__device__ __forceinline__ float fsigmoid(float z) { return 1.f / (1.f + __expf(-z)); }

// ---------------- prep kernels ----------------
__global__ void cvt_pad(float* __restrict__ dst, int DS,
                        const float* __restrict__ src, int SC, int rows)
{
    int idx = blockIdx.x * blockDim.x + threadIdx.x;
    if (idx >= rows * DS) return;
    int r = idx / DS, c = idx - r * DS;
    float v = (c < SC) ? src[(size_t)r * SC + c] : 0.f;
    dst[idx] = tf32r(v);
}

struct PrepJob {
    float* dst;
    const float* W;
    int Kp, N0;
    int b0, v0, b1, v1, b2, v2;
    int count;   // NP * Kp
};
struct PrepJobs { PrepJob j[6]; int cum[7]; };

// weights transposed to [N][Kp], tf32-rounded, zero-padded
__global__ void prep_all(PrepJobs J)
{
    int e = blockIdx.x * blockDim.x + threadIdx.x;
    if (e >= J.cum[6]) return;
    int ji = 0;
    while (e >= J.cum[ji + 1]) ji++;
    const PrepJob& p = J.j[ji];
    int idx = e - J.cum[ji];
    int n = idx / p.Kp, k = idx - n * p.Kp;
    int piece = (k >= 512) ? 2 : (k >= 256) ? 1 : 0;
    int off = k - ((piece == 2) ? 512 : piece * 256);
    int base  = (piece == 0) ? p.b0 : (piece == 1) ? p.b1 : p.b2;
    int valid = (piece == 0) ? p.v0 : (piece == 1) ? p.v1 : p.v2;
    float v = (off < valid && n < p.N0) ? p.W[(size_t)(base + off) * p.N0 + n] : 0.f;
    p.dst[idx] = tf32r(v);
}

// ---------------- TF32 fused GEMM (R5 2-stage skeleton, fp32 elements, BK=32) ----
// GATHER: 0 plain (astride); 2 [s1|eff|x]
// EPI: 0 bias?+fp32 store; 1 relu+LN -> tf32 plane; 2 tanh+LN+dot(W2)+sigmoid -> scalar
template<int BM, int BN, int KTOT, int GATHER, int EPI>
__global__ void __launch_bounds__(256) tgemm(
    const float* __restrict__ A1, const float* __restrict__ A2, const float* __restrict__ A3,
    const float* __restrict__ Bw,
    const float* __restrict__ bias, const float* __restrict__ gamma, const float* __restrict__ beta,
    const float* __restrict__ W2, const float* __restrict__ b2,
    float* __restrict__ Cf, float* __restrict__ Cpl,
    int N, int astride, int bstride, int cstride)
{
    constexpr int PADF = 36;                 // floats per 32-float stage row
    constexpr int NWM = BM / 32;
    constexpr int NWN = 8 / NWM;
    constexpr int NI  = BN / (8 * NWN);
    constexpr int NST = KTOT / 32;

    extern __shared__ __align__(16) float sm[];
    float* const Asm = sm;
    float* const Bsm = sm + 2 * BM * PADF;
    float* const red0 = sm + 2 * (BM + BN) * PADF;
    float* const red1 = red0 + BM * NWN;
    const uint32_t smb = smem_u32(sm);

    const int tid = threadIdx.x, w = tid >> 5, lane = tid & 31;
    const int g = lane >> 2, tq = lane & 3;
    const int wm = w % NWM, wn = w / NWM;
    const int row0 = blockIdx.x * BM;
    const int col0 = blockIdx.y * BN;
    Bw += (size_t)col0 * bstride;

    float acc[2][NI][4];
#pragma unroll
    for (int mi = 0; mi < 2; mi++)
#pragma unroll
        for (int ni = 0; ni < NI; ni++)
#pragma unroll
            for (int e = 0; e < 4; e++) acc[mi][ni][e] = 0.f;

    auto gatherA = [&](int gr, int k) -> const float* {
        if (GATHER == 0) {
            return A1 + (size_t)gr * astride + k;
        } else {
            if (k < 256) return A1 + (size_t)gr * 256 + k;
            if (k < 512) return A2 + (size_t)gr * 256 + (k - 256);
            return A3 + (size_t)gr * 576 + (k - 512);
        }
    };

    auto loadStage = [&](int t, int st) {
        int kb = t * 32;
#pragma unroll
        for (int u = tid; u < BM * 8; u += 256) {
            int r = u >> 3, cq = u & 7;
            cpa16(smb + (((st * BM + r) * PADF + cq * 4) << 2), gatherA(row0 + r, kb + cq * 4));
        }
#pragma unroll
        for (int u = tid; u < BN * 8; u += 256) {
            int r = u >> 3, cq = u & 7;
            cpa16(smb + ((2 * BM * PADF + (st * BN + r) * PADF + cq * 4) << 2),
                  Bw + (size_t)r * bstride + kb + cq * 4);
        }
    };

    auto compute = [&](int st) {
        const float* At = Asm + st * BM * PADF;
        const float* Bt = Bsm + st * BN * PADF;
#pragma unroll
        for (int kk = 0; kk < 4; kk++) {
            uint32_t a[2][4], b[NI][2];
            const int k = kk * 8 + tq;
#pragma unroll
            for (int mi = 0; mi < 2; mi++) {
                int r = wm * 32 + mi * 16 + g;
                a[mi][0] = __float_as_uint(At[r * PADF + k]);
                a[mi][1] = __float_as_uint(At[(r + 8) * PADF + k]);
                a[mi][2] = __float_as_uint(At[r * PADF + k + 4]);
                a[mi][3] = __float_as_uint(At[(r + 8) * PADF + k + 4]);
            }
#pragma unroll
            for (int ni = 0; ni < NI; ni++) {
                int r = wn * (NI * 8) + ni * 8 + g;
                b[ni][0] = __float_as_uint(Bt[r * PADF + k]);
                b[ni][1] = __float_as_uint(Bt[r * PADF + k + 4]);
            }
#pragma unroll
            for (int mi = 0; mi < 2; mi++)
#pragma unroll
                for (int ni = 0; ni < NI; ni++)
                    mma_tf32(acc[mi][ni], a[mi], b[ni]);
        }
    };

    // R5-proven 2-stage double buffer
    loadStage(0, 0); CP_COMMIT();
    for (int t = 0; t < NST; t++) {
        if (t + 1 < NST) { loadStage(t + 1, (t + 1) & 1); CP_COMMIT(); CP_WAIT(1); }
        else             { CP_WAIT(0); }
        __syncthreads();
        compute(t & 1);
        __syncthreads();
    }

    // ---------------- epilogues ----------------
    if (EPI == 0) {
#pragma unroll
        for (int mi = 0; mi < 2; mi++) {
            int r0 = row0 + wm * 32 + mi * 16 + g;
#pragma unroll
            for (int ni = 0; ni < NI; ni++) {
                int gc0 = col0 + wn * (NI * 8) + ni * 8 + tq * 2, gc1 = gc0 + 1;
                if (gc0 < N) {
                    float bv = bias ? bias[gc0] : 0.f;
                    Cf[(size_t)r0 * cstride + gc0]       = acc[mi][ni][0] + bv;
                    Cf[(size_t)(r0 + 8) * cstride + gc0] = acc[mi][ni][2] + bv;
                }
                if (gc1 < N) {
                    float bv = bias ? bias[gc1] : 0.f;
                    Cf[(size_t)r0 * cstride + gc1]       = acc[mi][ni][1] + bv;
                    Cf[(size_t)(r0 + 8) * cstride + gc1] = acc[mi][ni][3] + bv;
                }
            }
        }
        return;
    }

    // stat phase (EPI 1/2)
    float s[2][2] = {{0,0},{0,0}}, q[2][2] = {{0,0},{0,0}};
#pragma unroll
    for (int mi = 0; mi < 2; mi++)
#pragma unroll
        for (int ni = 0; ni < NI; ni++) {
            int c0 = wn * (NI * 8) + ni * 8 + tq * 2, c1 = c0 + 1;
            float b0v = (c0 < N) ? bias[c0] : 0.f;
            float b1v = (c1 < N) ? bias[c1] : 0.f;
            float v0 = acc[mi][ni][0] + b0v, v1 = acc[mi][ni][1] + b1v;
            float v2 = acc[mi][ni][2] + b0v, v3 = acc[mi][ni][3] + b1v;
            if (EPI == 2) {
                v0 = ftanh(v0); v1 = ftanh(v1); v2 = ftanh(v2); v3 = ftanh(v3);
            } else {
                v0 = fmaxf(v0, 0.f); v1 = fmaxf(v1, 0.f);
                v2 = fmaxf(v2, 0.f); v3 = fmaxf(v3, 0.f);
            }
            if (c0 >= N) { v0 = 0.f; v2 = 0.f; }
            if (c1 >= N) { v1 = 0.f; v3 = 0.f; }
            acc[mi][ni][0] = v0; acc[mi][ni][1] = v1;
            acc[mi][ni][2] = v2; acc[mi][ni][3] = v3;
            s[mi][0] += v0 + v1; q[mi][0] += v0 * v0 + v1 * v1;
            s[mi][1] += v2 + v3; q[mi][1] += v2 * v2 + v3 * v3;
        }
#pragma unroll
    for (int off = 1; off <= 2; off <<= 1)
#pragma unroll
        for (int mi = 0; mi < 2; mi++)
#pragma unroll
            for (int dr = 0; dr < 2; dr++) {
                s[mi][dr] += __shfl_xor_sync(0xffffffffu, s[mi][dr], off);
                q[mi][dr] += __shfl_xor_sync(0xffffffffu, q[mi][dr], off);
            }
    if (tq == 0)
#pragma unroll
        for (int mi = 0; mi < 2; mi++)
#pragma unroll
            for (int dr = 0; dr < 2; dr++) {
                int r = wm * 32 + mi * 16 + g + 8 * dr;
                red0[r * NWN + wn] = s[mi][dr];
                red1[r * NWN + wn] = q[mi][dr];
            }
    __syncthreads();
    float mu[2][2], rs[2][2];
    const float invN = 1.f / (float)N;
#pragma unroll
    for (int mi = 0; mi < 2; mi++)
#pragma unroll
        for (int dr = 0; dr < 2; dr++) {
            int r = wm * 32 + mi * 16 + g + 8 * dr;
            float ss = 0.f, qq = 0.f;
#pragma unroll
            for (int xx = 0; xx < NWN; xx++) { ss += red0[r * NWN + xx]; qq += red1[r * NWN + xx]; }
            mu[mi][dr] = ss * invN;
            rs[mi][dr] = rsqrtf(qq * invN - mu[mi][dr] * mu[mi][dr] + 1e-5f);
        }

    if (EPI == 1) {
#pragma unroll
        for (int mi = 0; mi < 2; mi++) {
            int gr0 = row0 + wm * 32 + mi * 16 + g;
#pragma unroll
            for (int ni = 0; ni < NI; ni++) {
                int c0 = wn * (NI * 8) + ni * 8 + tq * 2, c1 = c0 + 1;
                float g0 = (c0 < N) ? gamma[c0] : 0.f, g1 = (c1 < N) ? gamma[c1] : 0.f;
                float t0 = (c0 < N) ? beta[c0] : 0.f,  t1 = (c1 < N) ? beta[c1]  : 0.f;
#pragma unroll
                for (int dr = 0; dr < 2; dr++) {
                    int gr = gr0 + 8 * dr;
                    float w0 = (c0 < N) ? (acc[mi][ni][2*dr+0] - mu[mi][dr]) * rs[mi][dr] * g0 + t0 : 0.f;
                    float w1 = (c1 < N) ? (acc[mi][ni][2*dr+1] - mu[mi][dr]) * rs[mi][dr] * g1 + t1 : 0.f;
                    float2 wv = make_float2(tf32r(w0), tf32r(w1));
                    *(float2*)(Cpl + (size_t)gr * 256 + c0) = wv;
                }
            }
        }
        return;
    }

    // EPI == 2
    {
        float d[2][2] = {{0,0},{0,0}};
#pragma unroll
        for (int mi = 0; mi < 2; mi++)
#pragma unroll
            for (int ni = 0; ni < NI; ni++) {
                int c0 = wn * (NI * 8) + ni * 8 + tq * 2, c1 = c0 + 1;
#pragma unroll
                for (int dr = 0; dr < 2; dr++) {
                    if (c0 < N)
                        d[mi][dr] += ((acc[mi][ni][2*dr+0] - mu[mi][dr]) * rs[mi][dr] * gamma[c0] + beta[c0]) * W2[c0];
                    if (c1 < N)
                        d[mi][dr] += ((acc[mi][ni][2*dr+1] - mu[mi][dr]) * rs[mi][dr] * gamma[c1] + beta[c1]) * W2[c1];
                }
            }
#pragma unroll
        for (int off = 1; off <= 2; off <<= 1)
#pragma unroll
            for (int mi = 0; mi < 2; mi++)
#pragma unroll
                for (int dr = 0; dr < 2; dr++)
                    d[mi][dr] += __shfl_xor_sync(0xffffffffu, d[mi][dr], off);
        __syncthreads();
        if (tq == 0)
#pragma unroll
            for (int mi = 0; mi < 2; mi++)
#pragma unroll
                for (int dr = 0; dr < 2; dr++) {
                    int r = wm * 32 + mi * 16 + g + 8 * dr;
                    red0[r * NWN + wn] = d[mi][dr];
                }
        __syncthreads();
        if (wn == 0 && tq == 0) {
            float bb = b2[0];
#pragma unroll
            for (int mi = 0; mi < 2; mi++)
#pragma unroll
                for (int dr = 0; dr < 2; dr++) {
                    int r = wm * 32 + mi * 16 + g + 8 * dr;
                    float dd = 0.f;
#pragma unroll
                    for (int xx = 0; xx < NWN; xx++) dd += red0[r * NWN + xx];
                    Cf[row0 + r] = fsigmoid(dd + bb);
                }
        }
    }
}

// ---------------- core combine: core[b,i,j] = LN(relu(U[b,i] + V[b,j] + bias)) ----------------
__global__ void __launch_bounds__(256) combine_core(
    const float* __restrict__ UV, const float* __restrict__ bias,
    const float* __restrict__ gamma, const float* __restrict__ beta,
    float* __restrict__ core)
{
    const int r    = blockIdx.x * 8 + (threadIdx.x >> 5);
    const int lane = threadIdx.x & 31;
    const int b = r / 56, rem = r - b * 56;
    const int i = rem / 7, jj = rem - i * 7;
    const int j = jj + (jj >= i ? 1 : 0);
    const float4* up = (const float4*)(UV + (size_t)(b * 8 + i) * 512);
    const float4* vp = (const float4*)(UV + (size_t)(b * 8 + j) * 512 + 256);

    const int c0 = lane * 8;
    float v[8];
#pragma unroll
    for (int h = 0; h < 2; h++) {
        float4 u4 = up[lane * 2 + h];
        float4 v4 = vp[lane * 2 + h];
        float* vv = v + h * 4;
        vv[0] = u4.x + v4.x; vv[1] = u4.y + v4.y;
        vv[2] = u4.z + v4.z; vv[3] = u4.w + v4.w;
    }
    float s = 0.f, q = 0.f;
#pragma unroll
    for (int e = 0; e < 8; e++) {
        int c = c0 + e;
        float x = (c < 250) ? fmaxf(v[e] + bias[c], 0.f) : 0.f;
        v[e] = x;
        s += x; q += x * x;
    }
#pragma unroll
    for (int off = 16; off > 0; off >>= 1) {
        s += __shfl_xor_sync(0xffffffffu, s, off);
        q += __shfl_xor_sync(0xffffffffu, q, off);
    }
    float mu = s * (1.f / 250.f);
    float rs = rsqrtf(q * (1.f / 250.f) - mu * mu + 1e-5f);

    float4 o0, o1;
    float* op = &o0.x;
#pragma unroll
    for (int e = 0; e < 8; e++) {
        int c = c0 + e;
        float w = (c < 250) ? (v[e] - mu) * rs * gamma[c] + beta[c] : 0.f;
        ((e < 4) ? (&o0.x) : (&o1.x))[e & 3] = tf32r(w);
    }
    (void)op;
    float4* dst = (float4*)(core + (size_t)r * 256 + c0);
    dst[0] = o0; dst[1] = o1;
}

// effect: eff[bk][c] = sum_j ctx[bk*7+j][c] * att[bk*7+j], tf32-rounded
__global__ void effect3(const float* __restrict__ cx, const float* __restrict__ att,
                        float* __restrict__ eff)
{
    int bk = blockIdx.x, c = threadIdx.x;
    __shared__ float a[7];
    if (c < 7) a[c] = att[bk * 7 + c];
    __syncthreads();
    size_t base = (size_t)bk * 7 * 256 + c;
    float s = 0.f;
#pragma unroll
    for (int j = 0; j < 7; j++) s = fmaf(cx[base + j * 256], a[j], s);
    eff[(size_t)bk * 256 + c] = tf32r(s);
}

extern "C" void kernel_launch(void* const* d_in, const int* in_sizes, int n_in,
                              void* d_out, int out_size)
{
    const float* x       = (const float*)d_in[0];
    const float* state   = (const float*)d_in[1];
    const float* enc_W   = (const float*)d_in[2];
    const float* enc_b   = (const float*)d_in[3];
    const float* enc_g   = (const float*)d_in[4];
    const float* enc_bt  = (const float*)d_in[5];
    const float* core_W  = (const float*)d_in[6];
    const float* core_b  = (const float*)d_in[7];
    const float* core_g  = (const float*)d_in[8];
    const float* core_bt = (const float*)d_in[9];
    const float* ctx_W   = (const float*)d_in[10];
    const float* ctx_b   = (const float*)d_in[11];
    const float* ctx_g   = (const float*)d_in[12];
    const float* ctx_bt  = (const float*)d_in[13];
    const float* att_W1  = (const float*)d_in[14];
    const float* att_b1  = (const float*)d_in[15];
    const float* att_g   = (const float*)d_in[16];
    const float* att_bt  = (const float*)d_in[17];
    const float* att_W2  = (const float*)d_in[18];
    const float* att_b2  = (const float*)d_in[19];
    const float* out_W   = (const float*)d_in[20];
    const float* out_b   = (const float*)d_in[21];
    float* out = (float*)d_out;

    float *sp, *xp, *s1, *uv, *co, *cx, *att, *ef, *eW, *uvW, *xW, *aW, *oW;
    cudaGetSymbolAddress((void**)&sp, g_sp);   cudaGetSymbolAddress((void**)&xp, g_xp);
    cudaGetSymbolAddress((void**)&s1, g_s1);   cudaGetSymbolAddress((void**)&uv, g_uv);
    cudaGetSymbolAddress((void**)&co, g_co);   cudaGetSymbolAddress((void**)&cx, g_cx);
    cudaGetSymbolAddress((void**)&att, g_att); cudaGetSymbolAddress((void**)&ef, g_ef);
    cudaGetSymbolAddress((void**)&eW, g_eW);   cudaGetSymbolAddress((void**)&uvW, g_uvW);
    cudaGetSymbolAddress((void**)&xW, g_xW);   cudaGetSymbolAddress((void**)&aW, g_aW);
    cudaGetSymbolAddress((void**)&oW, g_oW);

    const int SM_STD = 2 * (64 + 256) * 36 * 4 + 2 * 64 * 4 * 4;    // 92160+2048 = 94208
    const int SM_ATT = 2 * (128 + 128) * 36 * 4 + 2 * 128 * 2 * 4;  // 73728+2048 = 75776
    cudaFuncSetAttribute((const void*)tgemm<64, 256, 256, 0, 1>,   cudaFuncAttributeMaxDynamicSharedMemorySize, SM_STD);
    cudaFuncSetAttribute((const void*)tgemm<64, 256, 256, 0, 0>,   cudaFuncAttributeMaxDynamicSharedMemorySize, SM_STD);
    cudaFuncSetAttribute((const void*)tgemm<128, 128, 256, 0, 2>,  cudaFuncAttributeMaxDynamicSharedMemorySize, SM_ATT);
    cudaFuncSetAttribute((const void*)tgemm<64, 256, 1088, 2, 0>,  cudaFuncAttributeMaxDynamicSharedMemorySize, SM_STD);

    // ---- prep ----
    cvt_pad<<<(16384 * 256) / 256, 256>>>(sp, 256, state, 250, 16384);
    cvt_pad<<<(16384 * 576) / 256, 256>>>(xp, 576, x, 576, 16384);

    PrepJobs J;
    auto mk = [](float* dst, const float* W, int Kp, int N0,
                 int b0, int v0, int b1, int v1, int b2, int v2, int NP) {
        PrepJob p; p.dst = dst; p.W = W; p.Kp = Kp; p.N0 = N0;
        p.b0 = b0; p.v0 = v0; p.b1 = b1; p.v1 = v1; p.b2 = b2; p.v2 = v2;
        p.count = NP * Kp; return p;
    };
    J.j[0] = mk(eW,              enc_W,  256, 250, 0, 250, 0, 0, 0, 0, 256);
    J.j[1] = mk(uvW,             core_W, 256, 250, 0, 250, 0, 0, 0, 0, 256);
    J.j[2] = mk(uvW + 256 * 256, core_W, 256, 250, 250, 250, 0, 0, 0, 0, 256);
    J.j[3] = mk(xW,              ctx_W,  256, 250, 0, 250, 0, 0, 0, 0, 256);
    J.j[4] = mk(aW,              att_W1, 256, 100, 0, 250, 0, 0, 0, 0, 128);
    J.j[5] = mk(oW,              out_W,  1088, 250, 0, 250, 250, 250, 500, 576, 256);
    J.cum[0] = 0;
    for (int i = 0; i < 6; i++) J.cum[i + 1] = J.cum[i] + J.j[i].count;
    prep_all<<<(J.cum[6] + 255) / 256, 256>>>(J);

    // 1. enc: s1 = LN(relu(state @ enc_W + b))  [tf32 plane]
    tgemm<64, 256, 256, 0, 1><<<BKTOT / 64, 256, SM_STD>>>(
        sp, nullptr, nullptr, eW,
        enc_b, enc_g, enc_bt, nullptr, nullptr,
        nullptr, s1, 250, 256, 256, 0);
    // 2. UV = s1 @ [W_top ++ W_bot]  (fp32, grid.y = 2)
    tgemm<64, 256, 256, 0, 0><<<dim3(BKTOT / 64, 2), 256, SM_STD>>>(
        s1, nullptr, nullptr, uvW,
        nullptr, nullptr, nullptr, nullptr, nullptr,
        uv, nullptr, 512, 256, 256, 512);
    // 3. core[b,i,j] = LN(relu(U[b,i] + V[b,j] + core_b))  [tf32 plane]
    combine_core<<<RR / 8, 256>>>(uv, core_b, core_g, core_bt, co);
    // 4. ctx = LN(relu(core @ ctx_W))  [tf32 plane]
    tgemm<64, 256, 256, 0, 1><<<RR / 64, 256, SM_STD>>>(
        co, nullptr, nullptr, xW,
        ctx_b, ctx_g, ctx_bt, nullptr, nullptr,
        nullptr, cx, 250, 256, 256, 0);
    // 5. att scores
    tgemm<128, 128, 256, 0, 2><<<RR / 128, 256, SM_ATT>>>(
        co, nullptr, nullptr, aW,
        att_b1, att_g, att_bt, att_W2, att_b2,
        att, nullptr, 100, 256, 256, 0);
    // 6. attention-weighted reduction
    effect3<<<BKTOT, 256>>>(cx, att, ef);
    // 7. out: [s1 | eff | x] @ out_W + b
    tgemm<64, 256, 1088, 2, 0><<<BKTOT / 64, 256, SM_STD>>>(
        s1, ef, xp, oW,
        out_b, nullptr, nullptr, nullptr, nullptr,
        out, nullptr, 250, 0, 1088, 250);
}